// round 13
// baseline (speedup 1.0000x reference)
#include <cuda_runtime.h>
#include <cuda_fp16.h>
#include <cstdint>

#define DIMC 768
#define HEADS 12
#define NTOK 64
#define DH 64

// ---------------- scratch (device globals) ----------------
__device__ __half g_qh[65536 * 768];
__device__ __half g_kh[65536 * 768];
__device__ __half g_vh[65536 * 768];
__device__ __half g_xh[65536 * 768];
__device__ __half g_ch[65536 * 768];
__device__ __half g_wh[2304 * 768];    // qkv weights transposed [n][k] fp16
__device__ __half g_wph[768 * 768];    // proj weight transposed fp16
__device__ float g_tbl[343 * 12];
__device__ float g_bias[12 * 64 * 64];

// ---------------- helpers ----------------
__device__ __forceinline__ uint32_t smem_u32(const void* p) {
    uint32_t a;
    asm("{ .reg .u64 t; cvta.to.shared.u64 t, %1; cvt.u32.u64 %0, t; }" : "=r"(a) : "l"(p));
    return a;
}
__device__ __forceinline__ void cp16(uint32_t s, const void* g) {
    asm volatile("cp.async.cg.shared.global [%0], [%1], 16;" ::"r"(s), "l"(g) : "memory");
}
__device__ __forceinline__ void cp_commit() { asm volatile("cp.async.commit_group;" ::: "memory"); }
__device__ __forceinline__ void cp_wait1() { asm volatile("cp.async.wait_group 1;" ::: "memory"); }
__device__ __forceinline__ void cp_wait0() { asm volatile("cp.async.wait_group 0;" ::: "memory"); }

__device__ __forceinline__ void ldsm4(uint32_t& r0, uint32_t& r1, uint32_t& r2, uint32_t& r3,
                                      uint32_t addr) {
    asm volatile("ldmatrix.sync.aligned.m8n8.x4.shared.b16 {%0,%1,%2,%3}, [%4];"
                 : "=r"(r0), "=r"(r1), "=r"(r2), "=r"(r3)
                 : "r"(addr));
}
__device__ __forceinline__ void ldsm4t(uint32_t& r0, uint32_t& r1, uint32_t& r2, uint32_t& r3,
                                       uint32_t addr) {
    asm volatile("ldmatrix.sync.aligned.m8n8.x4.trans.shared.b16 {%0,%1,%2,%3}, [%4];"
                 : "=r"(r0), "=r"(r1), "=r"(r2), "=r"(r3)
                 : "r"(addr));
}
__device__ __forceinline__ void mma_f16(float* c, const uint32_t* a, uint32_t b0, uint32_t b1) {
    asm volatile(
        "mma.sync.aligned.m16n8k16.row.col.f32.f16.f16.f32 "
        "{%0,%1,%2,%3},{%4,%5,%6,%7},{%8,%9},{%0,%1,%2,%3};"
        : "+f"(c[0]), "+f"(c[1]), "+f"(c[2]), "+f"(c[3])
        : "r"(a[0]), "r"(a[1]), "r"(a[2]), "r"(a[3]), "r"(b0), "r"(b1));
}

#define ASW(row, colbytes) ((row) * 128 + (((colbytes)) ^ (((row) & 7) << 4)))

// ================= hgemm (R8 proven): CTA 128x128, 8 warps x (64x32), 3-stage, 1 sync ======
#define BK 64
#define STG_BYTES 32768
#define NSTG 3
#define HG_SMEM (NSTG * STG_BYTES)
#define NKT (DIMC / BK)

template <typename OutT>
__global__ void __launch_bounds__(256, 2) hgemm(
    const __half* __restrict__ A, const __half* __restrict__ Bt, int nbn,
    const float* __restrict__ biasQ, const float* __restrict__ biasK,
    const float* __restrict__ biasV,
    OutT* __restrict__ out0, OutT* __restrict__ out1, OutT* __restrict__ out2) {
    extern __shared__ char smem[];
    const uint32_t sb = smem_u32(smem);
    const int tid = threadIdx.x;
    const int lane = tid & 31, warp = tid >> 5;
    const int bn = blockIdx.x % nbn, bm = blockIdx.x / nbn;
    const int wm = (warp & 1) * 64, wn = (warp >> 1) * 32;

    float acc[4][4][4];
#pragma unroll
    for (int i = 0; i < 4; i++)
#pragma unroll
        for (int j = 0; j < 4; j++)
#pragma unroll
            for (int k = 0; k < 4; k++) acc[i][j][k] = 0.f;

    const __half* Ab = A + (size_t)(bm * 128) * DIMC;
    const __half* Bb = Bt + (size_t)(bn * 128) * DIMC;

    auto load_stage = [&](int kt, int s) {
        const uint32_t st = sb + s * STG_BYTES;
#pragma unroll
        for (int i = 0; i < 8; i++) {
            const int c = tid + i * 256;
            if (c < 1024) {
                const int row = c >> 3, ch = c & 7;
                cp16(st + ASW(row, ch * 16), Ab + (size_t)row * DIMC + kt * BK + ch * 8);
            } else {
                const int cb = c - 1024;
                const int row = cb >> 3, ch = cb & 7;
                cp16(st + 16384 + ASW(row, ch * 16), Bb + (size_t)row * DIMC + kt * BK + ch * 8);
            }
        }
        cp_commit();
    };

    load_stage(0, 0);
    load_stage(1, 1);

    const int l15 = lane & 15, lh = (lane >> 4) * 16;
    int rs = 0, ws = 2;

    for (int kt = 0; kt < NKT; kt++) {
        cp_wait1();
        __syncthreads();
        if (kt + 2 < NKT) load_stage(kt + 2, ws);
        else cp_commit();

        const uint32_t sA = sb + rs * STG_BYTES;
        const uint32_t sB = sA + 16384;

#pragma unroll
        for (int ks = 0; ks < 4; ks++) {
            const int kb = ks * 32;
            uint32_t af[4][4], bf[2][4];
#pragma unroll
            for (int mt = 0; mt < 4; mt++) {
                const int row = wm + mt * 16 + l15;
                ldsm4(af[mt][0], af[mt][1], af[mt][2], af[mt][3], sA + ASW(row, kb + lh));
            }
#pragma unroll
            for (int bt = 0; bt < 2; bt++) {
                const int row = wn + bt * 16 + l15;
                ldsm4(bf[bt][0], bf[bt][1], bf[bt][2], bf[bt][3], sB + ASW(row, kb + lh));
            }
#pragma unroll
            for (int mt = 0; mt < 4; mt++) {
#pragma unroll
                for (int nt = 0; nt < 4; nt++) {
                    const int bt = nt >> 1, od = nt & 1;
                    mma_f16(acc[mt][nt], af[mt], bf[bt][od], bf[bt][od + 2]);
                }
            }
        }
        rs = (rs == 2) ? 0 : rs + 1;
        ws = (ws == 2) ? 0 : ws + 1;
    }

    const int matsel = (bn * 128) / DIMC;
    OutT* dst = matsel == 0 ? out0 : (matsel == 1 ? out1 : out2);
    const float* bp = matsel == 0 ? biasQ : (matsel == 1 ? biasK : biasV);
    const int lcbase = bn * 128 - matsel * DIMC;
#pragma unroll
    for (int mt = 0; mt < 4; mt++) {
#pragma unroll
        for (int nt = 0; nt < 4; nt++) {
            const int row = bm * 128 + wm + mt * 16 + (lane >> 2);
            const int tcol = wn + nt * 8 + (lane & 3) * 2;
            const int lc = lcbase + tcol;
            const float b0 = bp ? bp[lc] : 0.f;
            const float b1 = bp ? bp[lc + 1] : 0.f;
            if (sizeof(OutT) == 4) {
                float2 v0 = make_float2(acc[mt][nt][0] + b0, acc[mt][nt][1] + b1);
                float2 v1 = make_float2(acc[mt][nt][2] + b0, acc[mt][nt][3] + b1);
                *(float2*)&((float*)dst)[(size_t)row * DIMC + lc] = v0;
                *(float2*)&((float*)dst)[(size_t)(row + 8) * DIMC + lc] = v1;
            } else {
                __half2 h0 = __floats2half2_rn(acc[mt][nt][0] + b0, acc[mt][nt][1] + b1);
                __half2 h1 = __floats2half2_rn(acc[mt][nt][2] + b0, acc[mt][nt][3] + b1);
                *(__half2*)&((__half*)dst)[(size_t)row * DIMC + lc] = h0;
                *(__half2*)&((__half*)dst)[(size_t)(row + 8) * DIMC + lc] = h1;
            }
        }
    }
}

// ---------------- CPB MLP (launch 1) ----------------
__global__ void cpb_kernel(const float* __restrict__ tabl, const float* __restrict__ w1,
                           const float* __restrict__ b1, const float* __restrict__ w2,
                           const float* __restrict__ b2) {
    __shared__ float red[128 * 12];
    const int r = blockIdx.x;
    const int t = threadIdx.x;
    const float t0 = tabl[r * 3 + 0], t1 = tabl[r * 3 + 1], t2 = tabl[r * 3 + 2];
    float part[12];
#pragma unroll
    for (int hh = 0; hh < 12; hh++) part[hh] = 0.f;
    for (int j = t; j < 512; j += 128) {
        float h = t0 * w1[j] + t1 * w1[512 + j] + t2 * w1[1024 + j] + b1[j];
        h = fmaxf(h, 0.f);
#pragma unroll
        for (int hh = 0; hh < 12; hh++) part[hh] += h * w2[j * 12 + hh];
    }
#pragma unroll
    for (int hh = 0; hh < 12; hh++) red[t * 12 + hh] = part[hh];
    __syncthreads();
    if (t < 12) {
        float s = b2[t];
        for (int i = 0; i < 128; i++) s += red[i * 12 + t];
        g_tbl[r * 12 + t] = s;
    }
}

// ---------------- mega-prep (launch 2) ----------------
__global__ void prep_kernel(const int* __restrict__ idx,
                            const float4* __restrict__ x4, int nb_cvt,
                            const float* __restrict__ q_w, const float* __restrict__ k_w,
                            const float* __restrict__ v_w, const float* __restrict__ pw) {
    __shared__ float t[32][33];
    const int bid = blockIdx.x;
    const int tid = threadIdx.x;

    if (bid < 192) {
        const int g = bid * 256 + tid;
        const int h = g >> 12, ij = g & 4095;
        const float x = g_tbl[idx[ij] * 12 + h];
        g_bias[g] = 16.f / (1.f + __expf(-x));
        return;
    }
    if (bid < 192 + nb_cvt) {
        const int i = (bid - 192) * 256 + tid;
        const float4 v = x4[i];
        __half2 h0 = __floats2half2_rn(v.x, v.y);
        __half2 h1 = __floats2half2_rn(v.z, v.w);
        ((uint2*)g_xh)[i] = make_uint2(*(uint32_t*)&h0, *(uint32_t*)&h1);
        return;
    }
    const int tb = bid - 192 - nb_cvt;
    const int z = tb / 576, rem = tb - z * 576;
    const float* w = z == 0 ? q_w : (z == 1 ? k_w : (z == 2 ? v_w : pw));
    __half* d = z < 3 ? (g_wh + (size_t)z * DIMC * DIMC) : g_wph;
    const int bx = (rem % 24) * 32, by = (rem / 24) * 32;
    const int x = tid & 31, y = tid >> 5;
#pragma unroll
    for (int i = 0; i < 32; i += 8) t[y + i][x] = w[(size_t)(by + y + i) * DIMC + bx + x];
    __syncthreads();
#pragma unroll
    for (int i = 0; i < 32; i += 8)
        d[(size_t)(bx + y + i) * DIMC + by + x] = __float2half_rn(t[x][y + i]);
}

// ---------------- tensor-core attention (launch 4, profiled) ----------------
// 64 threads (2 warps) per (window,head); each warp owns 32 M-rows -> K/V ldsm 2x not 4x.
// smem: q/p overlay (8KB) + k (8KB) + v (8KB) + norms = 24.6KB
#define ATTN_SMEM (3 * 8192 + 512)

__global__ void __launch_bounds__(64, 8) attn_kernel(
    const __half* __restrict__ Q, const __half* __restrict__ K,
    const __half* __restrict__ V, const float* __restrict__ LS,
    __half* __restrict__ O) {
    extern __shared__ char sm[];
    const uint32_t sq = smem_u32(sm);
    const uint32_t sk = sq + 8192;
    const uint32_t sv = sk + 8192;
    const uint32_t sp = sq;                // P overlays Q (rows warp-private post-S)
    float* qn = (float*)(sm + 3 * 8192);
    float* kn = qn + 64;

    const int b = blockIdx.x, h = blockIdx.y;
    const int t = threadIdx.x;             // 0..63
    const int lane = t & 31, warp = t >> 5;
    const size_t base = ((size_t)b * NTOK) * DIMC + h * DH;

    // load q,k,v tiles: 24 passes x 64 threads x 16B
#pragma unroll
    for (int i = 0; i < 24; i++) {
        const int idx = t + i * 64;
        const int tens = idx >> 9, rem = idx & 511;
        const int row = rem >> 3, ch = rem & 7;
        const __half* src = (tens == 0 ? Q : (tens == 1 ? K : V)) + base + (size_t)row * DIMC + ch * 8;
        const uint32_t dst = (tens == 0 ? sq : (tens == 1 ? sk : sv)) + ASW(row, ch * 16);
        cp16(dst, src);
    }
    cp_commit();
    cp_wait0();
    __syncthreads();

    // norms: thread t does q-row t and k-row t
    {
        float sQ = 0.f, sK = 0.f;
#pragma unroll
        for (int ch = 0; ch < 8; ch++) {
            uint4 u;
            asm volatile("ld.shared.v4.u32 {%0,%1,%2,%3}, [%4];"
                         : "=r"(u.x), "=r"(u.y), "=r"(u.z), "=r"(u.w)
                         : "r"(sq + ASW(t, ch * 16)));
            const uint32_t uq[4] = {u.x, u.y, u.z, u.w};
#pragma unroll
            for (int q2 = 0; q2 < 4; q2++) {
                float2 f = __half22float2(*(const __half2*)&uq[q2]);
                sQ += f.x * f.x + f.y * f.y;
            }
            asm volatile("ld.shared.v4.u32 {%0,%1,%2,%3}, [%4];"
                         : "=r"(u.x), "=r"(u.y), "=r"(u.z), "=r"(u.w)
                         : "r"(sk + ASW(t, ch * 16)));
            const uint32_t uk[4] = {u.x, u.y, u.z, u.w};
#pragma unroll
            for (int q2 = 0; q2 < 4; q2++) {
                float2 f = __half22float2(*(const __half2*)&uk[q2]);
                sK += f.x * f.x + f.y * f.y;
            }
        }
        qn[t] = sqrtf(sQ);
        kn[t] = sqrtf(sK);
    }
    // no barrier: warp proceeds to S MMAs (reads own q rows + shared k)

    const float scale = fmaxf(LS[h], 0.01f);
    const float* bg = g_bias + h * 4096;
    const int m0 = warp * 32;
    const int l15 = lane & 15, lhb = (lane >> 4) * 16;

    // S = q @ k^T : 2 m16 tiles per warp sharing B fragments
    float acc[2][8][4];
#pragma unroll
    for (int m = 0; m < 2; m++)
#pragma unroll
        for (int n = 0; n < 8; n++)
#pragma unroll
            for (int k = 0; k < 4; k++) acc[m][n][k] = 0.f;
#pragma unroll
    for (int ks = 0; ks < 4; ks++) {
        const int kb = ks * 32;
        uint32_t af[2][4];
#pragma unroll
        for (int mt = 0; mt < 2; mt++)
            ldsm4(af[mt][0], af[mt][1], af[mt][2], af[mt][3],
                  sq + ASW(m0 + mt * 16 + l15, kb + lhb));
#pragma unroll
        for (int jb = 0; jb < 4; jb++) {
            uint32_t bfr[4];
            ldsm4(bfr[0], bfr[1], bfr[2], bfr[3], sk + ASW(jb * 16 + l15, kb + lhb));
#pragma unroll
            for (int mt = 0; mt < 2; mt++) {
                mma_f16(acc[mt][jb * 2], af[mt], bfr[0], bfr[2]);
                mma_f16(acc[mt][jb * 2 + 1], af[mt], bfr[1], bfr[3]);
            }
        }
    }

    __syncthreads();   // norms visible; all q reads done (overlay-safe)

    // epilogue + softmax + P store, per m-tile
    const int iq = lane >> 2;
#pragma unroll
    for (int mt = 0; mt < 2; mt++) {
        const int r0 = m0 + mt * 16 + iq;
        const float qn0 = qn[r0], qn1 = qn[r0 + 8];
#pragma unroll
        for (int nt = 0; nt < 8; nt++) {
            const int c0 = nt * 8 + (lane & 3) * 2;
            const float k0v = kn[c0], k1v = kn[c0 + 1];
            const float d00 = fmaxf(qn0 * k0v, 1e-6f), d01 = fmaxf(qn0 * k1v, 1e-6f);
            const float d10 = fmaxf(qn1 * k0v, 1e-6f), d11 = fmaxf(qn1 * k1v, 1e-6f);
            acc[mt][nt][0] = acc[mt][nt][0] / d00 * scale + bg[r0 * 64 + c0];
            acc[mt][nt][1] = acc[mt][nt][1] / d01 * scale + bg[r0 * 64 + c0 + 1];
            acc[mt][nt][2] = acc[mt][nt][2] / d10 * scale + bg[(r0 + 8) * 64 + c0];
            acc[mt][nt][3] = acc[mt][nt][3] / d11 * scale + bg[(r0 + 8) * 64 + c0 + 1];
        }

        float mx0 = -1e30f, mx1 = -1e30f;
#pragma unroll
        for (int nt = 0; nt < 8; nt++) {
            mx0 = fmaxf(mx0, fmaxf(acc[mt][nt][0], acc[mt][nt][1]));
            mx1 = fmaxf(mx1, fmaxf(acc[mt][nt][2], acc[mt][nt][3]));
        }
        mx0 = fmaxf(mx0, __shfl_xor_sync(0xffffffffu, mx0, 1));
        mx0 = fmaxf(mx0, __shfl_xor_sync(0xffffffffu, mx0, 2));
        mx1 = fmaxf(mx1, __shfl_xor_sync(0xffffffffu, mx1, 1));
        mx1 = fmaxf(mx1, __shfl_xor_sync(0xffffffffu, mx1, 2));
        float s0 = 0.f, s1 = 0.f;
#pragma unroll
        for (int nt = 0; nt < 8; nt++) {
            acc[mt][nt][0] = __expf(acc[mt][nt][0] - mx0);
            acc[mt][nt][1] = __expf(acc[mt][nt][1] - mx0);
            acc[mt][nt][2] = __expf(acc[mt][nt][2] - mx1);
            acc[mt][nt][3] = __expf(acc[mt][nt][3] - mx1);
            s0 += acc[mt][nt][0] + acc[mt][nt][1];
            s1 += acc[mt][nt][2] + acc[mt][nt][3];
        }
        s0 += __shfl_xor_sync(0xffffffffu, s0, 1);
        s0 += __shfl_xor_sync(0xffffffffu, s0, 2);
        s1 += __shfl_xor_sync(0xffffffffu, s1, 1);
        s1 += __shfl_xor_sync(0xffffffffu, s1, 2);
        const float inv0 = 1.f / s0, inv1 = 1.f / s1;

#pragma unroll
        for (int nt = 0; nt < 8; nt++) {
            const int c0 = nt * 8 + (lane & 3) * 2;
            __half2 h0 = __floats2half2_rn(acc[mt][nt][0] * inv0, acc[mt][nt][1] * inv0);
            __half2 h1 = __floats2half2_rn(acc[mt][nt][2] * inv1, acc[mt][nt][3] * inv1);
            asm volatile("st.shared.b32 [%0], %1;" ::"r"(sp + ASW(r0, c0 * 2)), "r"(*(uint32_t*)&h0));
            asm volatile("st.shared.b32 [%0], %1;" ::"r"(sp + ASW(r0 + 8, c0 * 2)), "r"(*(uint32_t*)&h1));
        }
    }
    __syncwarp();

    // O = P @ V : shared V fragments across both m tiles
    float oc[2][8][4];
#pragma unroll
    for (int m = 0; m < 2; m++)
#pragma unroll
        for (int n = 0; n < 8; n++)
#pragma unroll
            for (int k = 0; k < 4; k++) oc[m][n][k] = 0.f;
#pragma unroll
    for (int ks = 0; ks < 4; ks++) {
        const int kb = ks * 32;
        uint32_t af[2][4];
#pragma unroll
        for (int mt = 0; mt < 2; mt++)
            ldsm4(af[mt][0], af[mt][1], af[mt][2], af[mt][3],
                  sp + ASW(m0 + mt * 16 + l15, kb + lhb));
#pragma unroll
        for (int db = 0; db < 4; db++) {
            uint32_t bfr[4];
            ldsm4t(bfr[0], bfr[1], bfr[2], bfr[3], sv + ASW(ks * 16 + l15, db * 32 + lhb));
#pragma unroll
            for (int mt = 0; mt < 2; mt++) {
                mma_f16(oc[mt][db * 2], af[mt], bfr[0], bfr[1]);
                mma_f16(oc[mt][db * 2 + 1], af[mt], bfr[2], bfr[3]);
            }
        }
    }

#pragma unroll
    for (int mt = 0; mt < 2; mt++) {
        const int r0 = m0 + mt * 16 + iq;
#pragma unroll
        for (int nt = 0; nt < 8; nt++) {
            const int d0 = nt * 8 + (lane & 3) * 2;
            __half2 h0 = __floats2half2_rn(oc[mt][nt][0], oc[mt][nt][1]);
            __half2 h1 = __floats2half2_rn(oc[mt][nt][2], oc[mt][nt][3]);
            *(__half2*)&O[base + (size_t)r0 * DIMC + d0] = h0;
            *(__half2*)&O[base + (size_t)(r0 + 8) * DIMC + d0] = h1;
        }
    }
}

// ---------------- launch ----------------
extern "C" void kernel_launch(void* const* d_in, const int* in_sizes, int n_in,
                              void* d_out, int out_size) {
    const float* x   = (const float*)d_in[0];
    const float* q_w = (const float*)d_in[1];
    const float* q_b = (const float*)d_in[2];
    const float* k_w = (const float*)d_in[3];
    const float* v_w = (const float*)d_in[4];
    const float* v_b = (const float*)d_in[5];
    const float* cw1 = (const float*)d_in[6];
    const float* cb1 = (const float*)d_in[7];
    const float* cw2 = (const float*)d_in[8];
    const float* cb2 = (const float*)d_in[9];
    const float* ls  = (const float*)d_in[10];
    const float* pw  = (const float*)d_in[11];
    const float* pb  = (const float*)d_in[12];
    const float* tab = (const float*)d_in[13];
    const int*   idx = (const int*)d_in[14];
    float* out = (float*)d_out;

    const int rows = in_sizes[0] / DIMC;  // 65536
    const int B = rows / NTOK;            // 1024

    __half *dqh, *dkh, *dvh, *dxh, *dch, *dwh, *dwph;
    cudaGetSymbolAddress((void**)&dqh, g_qh);
    cudaGetSymbolAddress((void**)&dkh, g_kh);
    cudaGetSymbolAddress((void**)&dvh, g_vh);
    cudaGetSymbolAddress((void**)&dxh, g_xh);
    cudaGetSymbolAddress((void**)&dch, g_ch);
    cudaGetSymbolAddress((void**)&dwh, g_wh);
    cudaGetSymbolAddress((void**)&dwph, g_wph);

    cudaFuncSetAttribute(hgemm<__half>, cudaFuncAttributeMaxDynamicSharedMemorySize, HG_SMEM);
    cudaFuncSetAttribute(hgemm<float>, cudaFuncAttributeMaxDynamicSharedMemorySize, HG_SMEM);
    cudaFuncSetAttribute(attn_kernel, cudaFuncAttributeMaxDynamicSharedMemorySize, ATTN_SMEM);

    // 1: CPB MLP -> g_tbl
    cpb_kernel<<<343, 128>>>(tab, cw1, cb1, cw2, cb2);

    // 2: fused prep (bias gather + x->fp16 + 4 weight transposes)
    const int n4 = rows * DIMC / 4;
    const int nb_cvt = n4 / 256;
    prep_kernel<<<192 + nb_cvt + 4 * 576, 256>>>(idx, (const float4*)x, nb_cvt,
                                                 q_w, k_w, v_w, pw);

    // 3: fused QKV GEMM: [65536,768] x [768,2304] -> q,k,v (fp16)
    hgemm<__half><<<18 * (rows / 128), 256, HG_SMEM>>>(dxh, dwh, 18, q_b, nullptr, v_b,
                                                       dqh, dkh, dvh);

    // 4: tensor-core attention -> ctx (fp16)   [profiled launch]
    dim3 ga(B, HEADS);
    attn_kernel<<<ga, 64, ATTN_SMEM>>>(dqh, dkh, dvh, ls, dch);

    // 5: proj GEMM -> out (fp32)
    hgemm<float><<<6 * (rows / 128), 256, HG_SMEM>>>(dch, dwph, 6, pb, pb, pb,
                                                     out, out, out);
}

// round 14
// speedup vs baseline: 1.0332x; 1.0332x over previous
#include <cuda_runtime.h>
#include <cuda_fp16.h>
#include <cstdint>

#define DIMC 768
#define HEADS 12
#define NTOK 64
#define DH 64

// ---------------- scratch (device globals) ----------------
__device__ __half g_qh[65536 * 768];
__device__ __half g_kh[65536 * 768];
__device__ __half g_vh[65536 * 768];
__device__ __half g_xh[65536 * 768];
__device__ __half g_ch[65536 * 768];
__device__ __half g_wh[2304 * 768];    // qkv weights transposed [n][k] fp16
__device__ __half g_wph[768 * 768];    // proj weight transposed fp16
__device__ float g_tbl[343 * 12];
__device__ float4 g_biasf[12 * 4 * 8 * 32];   // fragment-ordered bias [h][warp][nt][lane]

// ---------------- helpers ----------------
__device__ __forceinline__ uint32_t smem_u32(const void* p) {
    uint32_t a;
    asm("{ .reg .u64 t; cvta.to.shared.u64 t, %1; cvt.u32.u64 %0, t; }" : "=r"(a) : "l"(p));
    return a;
}
__device__ __forceinline__ void cp16(uint32_t s, const void* g) {
    asm volatile("cp.async.cg.shared.global [%0], [%1], 16;" ::"r"(s), "l"(g) : "memory");
}
__device__ __forceinline__ void cp_commit() { asm volatile("cp.async.commit_group;" ::: "memory"); }
__device__ __forceinline__ void cp_wait1() { asm volatile("cp.async.wait_group 1;" ::: "memory"); }
__device__ __forceinline__ void cp_wait0() { asm volatile("cp.async.wait_group 0;" ::: "memory"); }

__device__ __forceinline__ void ldsm4(uint32_t& r0, uint32_t& r1, uint32_t& r2, uint32_t& r3,
                                      uint32_t addr) {
    asm volatile("ldmatrix.sync.aligned.m8n8.x4.shared.b16 {%0,%1,%2,%3}, [%4];"
                 : "=r"(r0), "=r"(r1), "=r"(r2), "=r"(r3)
                 : "r"(addr));
}
__device__ __forceinline__ void ldsm4t(uint32_t& r0, uint32_t& r1, uint32_t& r2, uint32_t& r3,
                                       uint32_t addr) {
    asm volatile("ldmatrix.sync.aligned.m8n8.x4.trans.shared.b16 {%0,%1,%2,%3}, [%4];"
                 : "=r"(r0), "=r"(r1), "=r"(r2), "=r"(r3)
                 : "r"(addr));
}
__device__ __forceinline__ void mma_f16(float* c, const uint32_t* a, uint32_t b0, uint32_t b1) {
    asm volatile(
        "mma.sync.aligned.m16n8k16.row.col.f32.f16.f16.f32 "
        "{%0,%1,%2,%3},{%4,%5,%6,%7},{%8,%9},{%0,%1,%2,%3};"
        : "+f"(c[0]), "+f"(c[1]), "+f"(c[2]), "+f"(c[3])
        : "r"(a[0]), "r"(a[1]), "r"(a[2]), "r"(a[3]), "r"(b0), "r"(b1));
}

#define ASW(row, colbytes) ((row) * 128 + (((colbytes)) ^ (((row) & 7) << 4)))

// ================= hgemm (R8 proven): CTA 128x128, 8 warps x (64x32), 3-stage, 1 sync ======
#define BK 64
#define STG_BYTES 32768
#define NSTG 3
#define HG_SMEM (NSTG * STG_BYTES)
#define NKT (DIMC / BK)

template <typename OutT>
__global__ void __launch_bounds__(256, 2) hgemm(
    const __half* __restrict__ A, const __half* __restrict__ Bt, int nbn,
    const float* __restrict__ biasQ, const float* __restrict__ biasK,
    const float* __restrict__ biasV,
    OutT* __restrict__ out0, OutT* __restrict__ out1, OutT* __restrict__ out2) {
    extern __shared__ char smem[];
    const uint32_t sb = smem_u32(smem);
    const int tid = threadIdx.x;
    const int lane = tid & 31, warp = tid >> 5;
    const int bn = blockIdx.x % nbn, bm = blockIdx.x / nbn;
    const int wm = (warp & 1) * 64, wn = (warp >> 1) * 32;

    float acc[4][4][4];
#pragma unroll
    for (int i = 0; i < 4; i++)
#pragma unroll
        for (int j = 0; j < 4; j++)
#pragma unroll
            for (int k = 0; k < 4; k++) acc[i][j][k] = 0.f;

    const __half* Ab = A + (size_t)(bm * 128) * DIMC;
    const __half* Bb = Bt + (size_t)(bn * 128) * DIMC;

    auto load_stage = [&](int kt, int s) {
        const uint32_t st = sb + s * STG_BYTES;
#pragma unroll
        for (int i = 0; i < 8; i++) {
            const int c = tid + i * 256;
            if (c < 1024) {
                const int row = c >> 3, ch = c & 7;
                cp16(st + ASW(row, ch * 16), Ab + (size_t)row * DIMC + kt * BK + ch * 8);
            } else {
                const int cb = c - 1024;
                const int row = cb >> 3, ch = cb & 7;
                cp16(st + 16384 + ASW(row, ch * 16), Bb + (size_t)row * DIMC + kt * BK + ch * 8);
            }
        }
        cp_commit();
    };

    load_stage(0, 0);
    load_stage(1, 1);

    const int l15 = lane & 15, lh = (lane >> 4) * 16;
    int rs = 0, ws = 2;

    for (int kt = 0; kt < NKT; kt++) {
        cp_wait1();
        __syncthreads();
        if (kt + 2 < NKT) load_stage(kt + 2, ws);
        else cp_commit();

        const uint32_t sA = sb + rs * STG_BYTES;
        const uint32_t sB = sA + 16384;

#pragma unroll
        for (int ks = 0; ks < 4; ks++) {
            const int kb = ks * 32;
            uint32_t af[4][4], bf[2][4];
#pragma unroll
            for (int mt = 0; mt < 4; mt++) {
                const int row = wm + mt * 16 + l15;
                ldsm4(af[mt][0], af[mt][1], af[mt][2], af[mt][3], sA + ASW(row, kb + lh));
            }
#pragma unroll
            for (int bt = 0; bt < 2; bt++) {
                const int row = wn + bt * 16 + l15;
                ldsm4(bf[bt][0], bf[bt][1], bf[bt][2], bf[bt][3], sB + ASW(row, kb + lh));
            }
#pragma unroll
            for (int mt = 0; mt < 4; mt++) {
#pragma unroll
                for (int nt = 0; nt < 4; nt++) {
                    const int bt = nt >> 1, od = nt & 1;
                    mma_f16(acc[mt][nt], af[mt], bf[bt][od], bf[bt][od + 2]);
                }
            }
        }
        rs = (rs == 2) ? 0 : rs + 1;
        ws = (ws == 2) ? 0 : ws + 1;
    }

    const int matsel = (bn * 128) / DIMC;
    OutT* dst = matsel == 0 ? out0 : (matsel == 1 ? out1 : out2);
    const float* bp = matsel == 0 ? biasQ : (matsel == 1 ? biasK : biasV);
    const int lcbase = bn * 128 - matsel * DIMC;
#pragma unroll
    for (int mt = 0; mt < 4; mt++) {
#pragma unroll
        for (int nt = 0; nt < 4; nt++) {
            const int row = bm * 128 + wm + mt * 16 + (lane >> 2);
            const int tcol = wn + nt * 8 + (lane & 3) * 2;
            const int lc = lcbase + tcol;
            const float b0 = bp ? bp[lc] : 0.f;
            const float b1 = bp ? bp[lc + 1] : 0.f;
            if (sizeof(OutT) == 4) {
                float2 v0 = make_float2(acc[mt][nt][0] + b0, acc[mt][nt][1] + b1);
                float2 v1 = make_float2(acc[mt][nt][2] + b0, acc[mt][nt][3] + b1);
                *(float2*)&((float*)dst)[(size_t)row * DIMC + lc] = v0;
                *(float2*)&((float*)dst)[(size_t)(row + 8) * DIMC + lc] = v1;
            } else {
                __half2 h0 = __floats2half2_rn(acc[mt][nt][0] + b0, acc[mt][nt][1] + b1);
                __half2 h1 = __floats2half2_rn(acc[mt][nt][2] + b0, acc[mt][nt][3] + b1);
                *(__half2*)&((__half*)dst)[(size_t)row * DIMC + lc] = h0;
                *(__half2*)&((__half*)dst)[(size_t)(row + 8) * DIMC + lc] = h1;
            }
        }
    }
}

// ---------------- CPB MLP (launch 1) ----------------
__global__ void cpb_kernel(const float* __restrict__ tabl, const float* __restrict__ w1,
                           const float* __restrict__ b1, const float* __restrict__ w2,
                           const float* __restrict__ b2) {
    __shared__ float red[128 * 12];
    const int r = blockIdx.x;
    const int t = threadIdx.x;
    const float t0 = tabl[r * 3 + 0], t1 = tabl[r * 3 + 1], t2 = tabl[r * 3 + 2];
    float part[12];
#pragma unroll
    for (int hh = 0; hh < 12; hh++) part[hh] = 0.f;
    for (int j = t; j < 512; j += 128) {
        float h = t0 * w1[j] + t1 * w1[512 + j] + t2 * w1[1024 + j] + b1[j];
        h = fmaxf(h, 0.f);
#pragma unroll
        for (int hh = 0; hh < 12; hh++) part[hh] += h * w2[j * 12 + hh];
    }
#pragma unroll
    for (int hh = 0; hh < 12; hh++) red[t * 12 + hh] = part[hh];
    __syncthreads();
    if (t < 12) {
        float s = b2[t];
        for (int i = 0; i < 128; i++) s += red[i * 12 + t];
        g_tbl[r * 12 + t] = s;
    }
}

// ---------------- mega-prep (launch 2): biasf + x->fp16 + 4 weight transposes ----------------
// region A: biasf  : 48 blocks (12*4*8*32 float4 = 12288 threads)
// region B: cvtx   : nb_cvt blocks
// region C: trwh   : 4*576 blocks
__global__ void prep_kernel(const int* __restrict__ idx,
                            const float4* __restrict__ x4, int nb_cvt,
                            const float* __restrict__ q_w, const float* __restrict__ k_w,
                            const float* __restrict__ v_w, const float* __restrict__ pw) {
    __shared__ float t[32][33];
    const int bid = blockIdx.x;
    const int tid = threadIdx.x;

    if (bid < 48) {
        const int gid = bid * 256 + tid;           // 0..12287
        const int h = gid >> 10;                   // /1024
        const int rem = gid & 1023;
        const int w = rem >> 8;                    // /256
        const int rem2 = rem & 255;
        const int nt = rem2 >> 5, lane = rem2 & 31;
        const int r0 = w * 16 + (lane >> 2);
        const int c0 = nt * 8 + (lane & 3) * 2;
        float4 v;
        {
            float xx = g_tbl[idx[r0 * 64 + c0] * 12 + h];
            v.x = 16.f / (1.f + __expf(-xx));
            xx = g_tbl[idx[r0 * 64 + c0 + 1] * 12 + h];
            v.y = 16.f / (1.f + __expf(-xx));
            xx = g_tbl[idx[(r0 + 8) * 64 + c0] * 12 + h];
            v.z = 16.f / (1.f + __expf(-xx));
            xx = g_tbl[idx[(r0 + 8) * 64 + c0 + 1] * 12 + h];
            v.w = 16.f / (1.f + __expf(-xx));
        }
        g_biasf[gid] = v;
        return;
    }
    if (bid < 48 + nb_cvt) {
        const int i = (bid - 48) * 256 + tid;
        const float4 v = x4[i];
        __half2 h0 = __floats2half2_rn(v.x, v.y);
        __half2 h1 = __floats2half2_rn(v.z, v.w);
        ((uint2*)g_xh)[i] = make_uint2(*(uint32_t*)&h0, *(uint32_t*)&h1);
        return;
    }
    const int tb = bid - 48 - nb_cvt;
    const int z = tb / 576, rem = tb - z * 576;
    const float* w = z == 0 ? q_w : (z == 1 ? k_w : (z == 2 ? v_w : pw));
    __half* d = z < 3 ? (g_wh + (size_t)z * DIMC * DIMC) : g_wph;
    const int bx = (rem % 24) * 32, by = (rem / 24) * 32;
    const int x = tid & 31, y = tid >> 5;
#pragma unroll
    for (int i = 0; i < 32; i += 8) t[y + i][x] = w[(size_t)(by + y + i) * DIMC + bx + x];
    __syncthreads();
#pragma unroll
    for (int i = 0; i < 32; i += 8)
        d[(size_t)(bx + y + i) * DIMC + by + x] = __float2half_rn(t[x][y + i]);
}

// ---------------- tensor-core attention (R11 shape + fragment-ordered bias) ----------------
// smem: q/p overlay (8KB) + k (8KB) + v (8KB) + norms -> 24.6KB
#define ATTN_SMEM (3 * 8192 + 512)

__global__ void __launch_bounds__(128) attn_kernel(
    const __half* __restrict__ Q, const __half* __restrict__ K,
    const __half* __restrict__ V, const float* __restrict__ LS,
    __half* __restrict__ O) {
    extern __shared__ char sm[];
    const uint32_t sq = smem_u32(sm);      // q tile; later overlaid by P tile
    const uint32_t sk = sq + 8192;
    const uint32_t sv = sk + 8192;
    const uint32_t sp = sq;                // overlay: safe, rows warp-private post-S
    float* qn = (float*)(sm + 3 * 8192);
    float* kn = qn + 64;

    const int b = blockIdx.x, h = blockIdx.y;
    const int t = threadIdx.x;
    const int lane = t & 31, warp = t >> 5;
    const size_t base = ((size_t)b * NTOK) * DIMC + h * DH;

#pragma unroll
    for (int i = 0; i < 12; i++) {
        const int idx = t + i * 128;
        const int tens = idx >> 9, rem = idx & 511;
        const int row = rem >> 3, ch = rem & 7;
        const __half* src = (tens == 0 ? Q : (tens == 1 ? K : V)) + base + (size_t)row * DIMC + ch * 8;
        const uint32_t dst = (tens == 0 ? sq : (tens == 1 ? sk : sv)) + ASW(row, ch * 16);
        cp16(dst, src);
    }
    cp_commit();
    cp_wait0();
    __syncthreads();   // all tiles resident

    // norms
    {
        const int row = t & 63;
        const uint32_t src = (t < 64 ? sq : sk);
        float s = 0.f;
#pragma unroll
        for (int ch = 0; ch < 8; ch++) {
            uint4 u;
            asm volatile("ld.shared.v4.u32 {%0,%1,%2,%3}, [%4];"
                         : "=r"(u.x), "=r"(u.y), "=r"(u.z), "=r"(u.w)
                         : "r"(src + ASW(row, ch * 16)));
            const uint32_t uu[4] = {u.x, u.y, u.z, u.w};
#pragma unroll
            for (int q2 = 0; q2 < 4; q2++) {
                float2 f = __half22float2(*(const __half2*)&uu[q2]);
                s += f.x * f.x + f.y * f.y;
            }
        }
        if (t < 64) qn[row] = sqrtf(s);
        else kn[row] = sqrtf(s);
    }
    // no barrier: warp proceeds to S MMAs

    const float scale = fmaxf(LS[h], 0.01f);
    const int m0 = warp * 16;
    const int l15 = lane & 15, lhb = (lane >> 4) * 16;

    float acc[8][4];
#pragma unroll
    for (int n = 0; n < 8; n++)
#pragma unroll
        for (int k = 0; k < 4; k++) acc[n][k] = 0.f;
#pragma unroll
    for (int ks = 0; ks < 4; ks++) {
        const int kb = ks * 32;
        uint32_t a[4];
        ldsm4(a[0], a[1], a[2], a[3], sq + ASW(m0 + l15, kb + lhb));
#pragma unroll
        for (int jb = 0; jb < 4; jb++) {
            uint32_t bfr[4];
            ldsm4(bfr[0], bfr[1], bfr[2], bfr[3], sk + ASW(jb * 16 + l15, kb + lhb));
            mma_f16(acc[jb * 2], a, bfr[0], bfr[2]);
            mma_f16(acc[jb * 2 + 1], a, bfr[1], bfr[3]);
        }
    }

    __syncthreads();   // norms visible; q reads done (overlay-safe)

    const int i0 = m0 + (lane >> 2);
    const float qn0 = qn[i0], qn1 = qn[i0 + 8];
    const float4* bgf = g_biasf + ((h * 4 + warp) * 8) * 32;
#pragma unroll
    for (int nt = 0; nt < 8; nt++) {
        const int c0 = nt * 8 + (lane & 3) * 2;
        const float4 bv = bgf[nt * 32 + lane];
        const float k0v = kn[c0], k1v = kn[c0 + 1];
        const float d00 = fmaxf(qn0 * k0v, 1e-6f), d01 = fmaxf(qn0 * k1v, 1e-6f);
        const float d10 = fmaxf(qn1 * k0v, 1e-6f), d11 = fmaxf(qn1 * k1v, 1e-6f);
        acc[nt][0] = acc[nt][0] / d00 * scale + bv.x;
        acc[nt][1] = acc[nt][1] / d01 * scale + bv.y;
        acc[nt][2] = acc[nt][2] / d10 * scale + bv.z;
        acc[nt][3] = acc[nt][3] / d11 * scale + bv.w;
    }

    float mx0 = -1e30f, mx1 = -1e30f;
#pragma unroll
    for (int nt = 0; nt < 8; nt++) {
        mx0 = fmaxf(mx0, fmaxf(acc[nt][0], acc[nt][1]));
        mx1 = fmaxf(mx1, fmaxf(acc[nt][2], acc[nt][3]));
    }
    mx0 = fmaxf(mx0, __shfl_xor_sync(0xffffffffu, mx0, 1));
    mx0 = fmaxf(mx0, __shfl_xor_sync(0xffffffffu, mx0, 2));
    mx1 = fmaxf(mx1, __shfl_xor_sync(0xffffffffu, mx1, 1));
    mx1 = fmaxf(mx1, __shfl_xor_sync(0xffffffffu, mx1, 2));
    float s0 = 0.f, s1 = 0.f;
#pragma unroll
    for (int nt = 0; nt < 8; nt++) {
        acc[nt][0] = __expf(acc[nt][0] - mx0);
        acc[nt][1] = __expf(acc[nt][1] - mx0);
        acc[nt][2] = __expf(acc[nt][2] - mx1);
        acc[nt][3] = __expf(acc[nt][3] - mx1);
        s0 += acc[nt][0] + acc[nt][1];
        s1 += acc[nt][2] + acc[nt][3];
    }
    s0 += __shfl_xor_sync(0xffffffffu, s0, 1);
    s0 += __shfl_xor_sync(0xffffffffu, s0, 2);
    s1 += __shfl_xor_sync(0xffffffffu, s1, 1);
    s1 += __shfl_xor_sync(0xffffffffu, s1, 2);
    const float inv0 = 1.f / s0, inv1 = 1.f / s1;

#pragma unroll
    for (int nt = 0; nt < 8; nt++) {
        const int c0 = nt * 8 + (lane & 3) * 2;
        __half2 h0 = __floats2half2_rn(acc[nt][0] * inv0, acc[nt][1] * inv0);
        __half2 h1 = __floats2half2_rn(acc[nt][2] * inv1, acc[nt][3] * inv1);
        asm volatile("st.shared.b32 [%0], %1;" ::"r"(sp + ASW(i0, c0 * 2)), "r"(*(uint32_t*)&h0));
        asm volatile("st.shared.b32 [%0], %1;" ::"r"(sp + ASW(i0 + 8, c0 * 2)), "r"(*(uint32_t*)&h1));
    }
    __syncwarp();

    float oc[8][4];
#pragma unroll
    for (int n = 0; n < 8; n++)
#pragma unroll
        for (int k = 0; k < 4; k++) oc[n][k] = 0.f;
#pragma unroll
    for (int ks = 0; ks < 4; ks++) {
        const int kb = ks * 32;
        uint32_t a[4];
        ldsm4(a[0], a[1], a[2], a[3], sp + ASW(m0 + l15, kb + lhb));
#pragma unroll
        for (int db = 0; db < 4; db++) {
            uint32_t bfr[4];
            ldsm4t(bfr[0], bfr[1], bfr[2], bfr[3], sv + ASW(ks * 16 + l15, db * 32 + lhb));
            mma_f16(oc[db * 2], a, bfr[0], bfr[1]);
            mma_f16(oc[db * 2 + 1], a, bfr[2], bfr[3]);
        }
    }

#pragma unroll
    for (int nt = 0; nt < 8; nt++) {
        const int d0 = nt * 8 + (lane & 3) * 2;
        __half2 h0 = __floats2half2_rn(oc[nt][0], oc[nt][1]);
        __half2 h1 = __floats2half2_rn(oc[nt][2], oc[nt][3]);
        *(__half2*)&O[base + (size_t)i0 * DIMC + d0] = h0;
        *(__half2*)&O[base + (size_t)(i0 + 8) * DIMC + d0] = h1;
    }
}

// ---------------- launch ----------------
extern "C" void kernel_launch(void* const* d_in, const int* in_sizes, int n_in,
                              void* d_out, int out_size) {
    const float* x   = (const float*)d_in[0];
    const float* q_w = (const float*)d_in[1];
    const float* q_b = (const float*)d_in[2];
    const float* k_w = (const float*)d_in[3];
    const float* v_w = (const float*)d_in[4];
    const float* v_b = (const float*)d_in[5];
    const float* cw1 = (const float*)d_in[6];
    const float* cb1 = (const float*)d_in[7];
    const float* cw2 = (const float*)d_in[8];
    const float* cb2 = (const float*)d_in[9];
    const float* ls  = (const float*)d_in[10];
    const float* pw  = (const float*)d_in[11];
    const float* pb  = (const float*)d_in[12];
    const float* tab = (const float*)d_in[13];
    const int*   idx = (const int*)d_in[14];
    float* out = (float*)d_out;

    const int rows = in_sizes[0] / DIMC;  // 65536
    const int B = rows / NTOK;            // 1024

    __half *dqh, *dkh, *dvh, *dxh, *dch, *dwh, *dwph;
    cudaGetSymbolAddress((void**)&dqh, g_qh);
    cudaGetSymbolAddress((void**)&dkh, g_kh);
    cudaGetSymbolAddress((void**)&dvh, g_vh);
    cudaGetSymbolAddress((void**)&dxh, g_xh);
    cudaGetSymbolAddress((void**)&dch, g_ch);
    cudaGetSymbolAddress((void**)&dwh, g_wh);
    cudaGetSymbolAddress((void**)&dwph, g_wph);

    cudaFuncSetAttribute(hgemm<__half>, cudaFuncAttributeMaxDynamicSharedMemorySize, HG_SMEM);
    cudaFuncSetAttribute(hgemm<float>, cudaFuncAttributeMaxDynamicSharedMemorySize, HG_SMEM);
    cudaFuncSetAttribute(attn_kernel, cudaFuncAttributeMaxDynamicSharedMemorySize, ATTN_SMEM);

    // 1: CPB MLP -> g_tbl
    cpb_kernel<<<343, 128>>>(tab, cw1, cb1, cw2, cb2);

    // 2: fused prep (fragment-ordered bias + x->fp16 + 4 weight transposes)
    const int n4 = rows * DIMC / 4;
    const int nb_cvt = n4 / 256;
    prep_kernel<<<48 + nb_cvt + 4 * 576, 256>>>(idx, (const float4*)x, nb_cvt,
                                                q_w, k_w, v_w, pw);

    // 3: fused QKV GEMM: [65536,768] x [768,2304] -> q,k,v (fp16)
    hgemm<__half><<<18 * (rows / 128), 256, HG_SMEM>>>(dxh, dwh, 18, q_b, nullptr, v_b,
                                                       dqh, dkh, dvh);

    // 4: tensor-core attention -> ctx (fp16)   [profiled launch]
    dim3 ga(B, HEADS);
    attn_kernel<<<ga, 128, ATTN_SMEM>>>(dqh, dkh, dvh, ls, dch);

    // 5: proj GEMM -> out (fp32)
    hgemm<float><<<6 * (rows / 128), 256, HG_SMEM>>>(dch, dwph, 6, pb, pb, pb,
                                                     out, out, out);
}

// round 15
// speedup vs baseline: 1.0533x; 1.0195x over previous
#include <cuda_runtime.h>
#include <cuda_fp16.h>
#include <cstdint>

#define DIMC 768
#define HEADS 12
#define NTOK 64
#define DH 64

// ---------------- scratch (device globals) ----------------
__device__ __half g_qh[65536 * 768];
__device__ __half g_kh[65536 * 768];
__device__ __half g_vh[65536 * 768];
__device__ __half g_xh[65536 * 768];
__device__ __half g_ch[65536 * 768];
__device__ __half g_wh[2304 * 768];    // qkv weights transposed [n][k] fp16
__device__ __half g_wph[768 * 768];    // proj weight transposed fp16
__device__ float g_tbl[343 * 12];
__device__ float4 g_biasf[12 * 4 * 8 * 32];   // fragment-ordered bias [h][warp][nt][lane]

// ---------------- helpers ----------------
__device__ __forceinline__ uint32_t smem_u32(const void* p) {
    uint32_t a;
    asm("{ .reg .u64 t; cvta.to.shared.u64 t, %1; cvt.u32.u64 %0, t; }" : "=r"(a) : "l"(p));
    return a;
}
__device__ __forceinline__ void cp16(uint32_t s, const void* g) {
    asm volatile("cp.async.cg.shared.global [%0], [%1], 16;" ::"r"(s), "l"(g) : "memory");
}
__device__ __forceinline__ void cp_commit() { asm volatile("cp.async.commit_group;" ::: "memory"); }
__device__ __forceinline__ void cp_wait1() { asm volatile("cp.async.wait_group 1;" ::: "memory"); }
__device__ __forceinline__ void cp_wait0() { asm volatile("cp.async.wait_group 0;" ::: "memory"); }

__device__ __forceinline__ void ldsm4(uint32_t& r0, uint32_t& r1, uint32_t& r2, uint32_t& r3,
                                      uint32_t addr) {
    asm volatile("ldmatrix.sync.aligned.m8n8.x4.shared.b16 {%0,%1,%2,%3}, [%4];"
                 : "=r"(r0), "=r"(r1), "=r"(r2), "=r"(r3)
                 : "r"(addr));
}
__device__ __forceinline__ void ldsm4t(uint32_t& r0, uint32_t& r1, uint32_t& r2, uint32_t& r3,
                                       uint32_t addr) {
    asm volatile("ldmatrix.sync.aligned.m8n8.x4.trans.shared.b16 {%0,%1,%2,%3}, [%4];"
                 : "=r"(r0), "=r"(r1), "=r"(r2), "=r"(r3)
                 : "r"(addr));
}
__device__ __forceinline__ void mma_f16(float* c, const uint32_t* a, uint32_t b0, uint32_t b1) {
    asm volatile(
        "mma.sync.aligned.m16n8k16.row.col.f32.f16.f16.f32 "
        "{%0,%1,%2,%3},{%4,%5,%6,%7},{%8,%9},{%0,%1,%2,%3};"
        : "+f"(c[0]), "+f"(c[1]), "+f"(c[2]), "+f"(c[3])
        : "r"(a[0]), "r"(a[1]), "r"(a[2]), "r"(a[3]), "r"(b0), "r"(b1));
}

#define ASW(row, colbytes) ((row) * 128 + (((colbytes)) ^ (((row) & 7) << 4)))

// ================= hgemm (R8 proven): CTA 128x128, 8 warps x (64x32), 3-stage, 1 sync ======
#define BK 64
#define STG_BYTES 32768
#define NSTG 3
#define HG_SMEM (NSTG * STG_BYTES)
#define NKT (DIMC / BK)

template <typename OutT>
__global__ void __launch_bounds__(256, 2) hgemm(
    const __half* __restrict__ A, const __half* __restrict__ Bt, int nbn,
    const float* __restrict__ biasQ, const float* __restrict__ biasK,
    const float* __restrict__ biasV,
    OutT* __restrict__ out0, OutT* __restrict__ out1, OutT* __restrict__ out2) {
    extern __shared__ char smem[];
    const uint32_t sb = smem_u32(smem);
    const int tid = threadIdx.x;
    const int lane = tid & 31, warp = tid >> 5;
    const int bn = blockIdx.x % nbn, bm = blockIdx.x / nbn;
    const int wm = (warp & 1) * 64, wn = (warp >> 1) * 32;

    float acc[4][4][4];
#pragma unroll
    for (int i = 0; i < 4; i++)
#pragma unroll
        for (int j = 0; j < 4; j++)
#pragma unroll
            for (int k = 0; k < 4; k++) acc[i][j][k] = 0.f;

    const __half* Ab = A + (size_t)(bm * 128) * DIMC;
    const __half* Bb = Bt + (size_t)(bn * 128) * DIMC;

    auto load_stage = [&](int kt, int s) {
        const uint32_t st = sb + s * STG_BYTES;
#pragma unroll
        for (int i = 0; i < 8; i++) {
            const int c = tid + i * 256;
            if (c < 1024) {
                const int row = c >> 3, ch = c & 7;
                cp16(st + ASW(row, ch * 16), Ab + (size_t)row * DIMC + kt * BK + ch * 8);
            } else {
                const int cb = c - 1024;
                const int row = cb >> 3, ch = cb & 7;
                cp16(st + 16384 + ASW(row, ch * 16), Bb + (size_t)row * DIMC + kt * BK + ch * 8);
            }
        }
        cp_commit();
    };

    load_stage(0, 0);
    load_stage(1, 1);

    const int l15 = lane & 15, lh = (lane >> 4) * 16;
    int rs = 0, ws = 2;

    for (int kt = 0; kt < NKT; kt++) {
        cp_wait1();
        __syncthreads();
        if (kt + 2 < NKT) load_stage(kt + 2, ws);
        else cp_commit();

        const uint32_t sA = sb + rs * STG_BYTES;
        const uint32_t sB = sA + 16384;

#pragma unroll
        for (int ks = 0; ks < 4; ks++) {
            const int kb = ks * 32;
            uint32_t af[4][4], bf[2][4];
#pragma unroll
            for (int mt = 0; mt < 4; mt++) {
                const int row = wm + mt * 16 + l15;
                ldsm4(af[mt][0], af[mt][1], af[mt][2], af[mt][3], sA + ASW(row, kb + lh));
            }
#pragma unroll
            for (int bt = 0; bt < 2; bt++) {
                const int row = wn + bt * 16 + l15;
                ldsm4(bf[bt][0], bf[bt][1], bf[bt][2], bf[bt][3], sB + ASW(row, kb + lh));
            }
#pragma unroll
            for (int mt = 0; mt < 4; mt++) {
#pragma unroll
                for (int nt = 0; nt < 4; nt++) {
                    const int bt = nt >> 1, od = nt & 1;
                    mma_f16(acc[mt][nt], af[mt], bf[bt][od], bf[bt][od + 2]);
                }
            }
        }
        rs = (rs == 2) ? 0 : rs + 1;
        ws = (ws == 2) ? 0 : ws + 1;
    }

    const int matsel = (bn * 128) / DIMC;
    OutT* dst = matsel == 0 ? out0 : (matsel == 1 ? out1 : out2);
    const float* bp = matsel == 0 ? biasQ : (matsel == 1 ? biasK : biasV);
    const int lcbase = bn * 128 - matsel * DIMC;
#pragma unroll
    for (int mt = 0; mt < 4; mt++) {
#pragma unroll
        for (int nt = 0; nt < 4; nt++) {
            const int row = bm * 128 + wm + mt * 16 + (lane >> 2);
            const int tcol = wn + nt * 8 + (lane & 3) * 2;
            const int lc = lcbase + tcol;
            const float b0 = bp ? bp[lc] : 0.f;
            const float b1 = bp ? bp[lc + 1] : 0.f;
            if (sizeof(OutT) == 4) {
                float2 v0 = make_float2(acc[mt][nt][0] + b0, acc[mt][nt][1] + b1);
                float2 v1 = make_float2(acc[mt][nt][2] + b0, acc[mt][nt][3] + b1);
                *(float2*)&((float*)dst)[(size_t)row * DIMC + lc] = v0;
                *(float2*)&((float*)dst)[(size_t)(row + 8) * DIMC + lc] = v1;
            } else {
                __half2 h0 = __floats2half2_rn(acc[mt][nt][0] + b0, acc[mt][nt][1] + b1);
                __half2 h1 = __floats2half2_rn(acc[mt][nt][2] + b0, acc[mt][nt][3] + b1);
                *(__half2*)&((__half*)dst)[(size_t)row * DIMC + lc] = h0;
                *(__half2*)&((__half*)dst)[(size_t)(row + 8) * DIMC + lc] = h1;
            }
        }
    }
}

// ---------------- CPB MLP (launch 1) ----------------
__global__ void cpb_kernel(const float* __restrict__ tabl, const float* __restrict__ w1,
                           const float* __restrict__ b1, const float* __restrict__ w2,
                           const float* __restrict__ b2) {
    __shared__ float red[128 * 12];
    const int r = blockIdx.x;
    const int t = threadIdx.x;
    const float t0 = tabl[r * 3 + 0], t1 = tabl[r * 3 + 1], t2 = tabl[r * 3 + 2];
    float part[12];
#pragma unroll
    for (int hh = 0; hh < 12; hh++) part[hh] = 0.f;
    for (int j = t; j < 512; j += 128) {
        float h = t0 * w1[j] + t1 * w1[512 + j] + t2 * w1[1024 + j] + b1[j];
        h = fmaxf(h, 0.f);
#pragma unroll
        for (int hh = 0; hh < 12; hh++) part[hh] += h * w2[j * 12 + hh];
    }
#pragma unroll
    for (int hh = 0; hh < 12; hh++) red[t * 12 + hh] = part[hh];
    __syncthreads();
    if (t < 12) {
        float s = b2[t];
        for (int i = 0; i < 128; i++) s += red[i * 12 + t];
        g_tbl[r * 12 + t] = s;
    }
}

// ---------------- mega-prep (launch 2): biasf + x->fp16 + 4 weight transposes ----------------
__global__ void prep_kernel(const int* __restrict__ idx,
                            const float4* __restrict__ x4, int nb_cvt,
                            const float* __restrict__ q_w, const float* __restrict__ k_w,
                            const float* __restrict__ v_w, const float* __restrict__ pw) {
    __shared__ float t[32][33];
    const int bid = blockIdx.x;
    const int tid = threadIdx.x;

    if (bid < 48) {
        const int gid = bid * 256 + tid;           // 0..12287
        const int h = gid >> 10;
        const int rem = gid & 1023;
        const int w = rem >> 8;
        const int rem2 = rem & 255;
        const int nt = rem2 >> 5, lane = rem2 & 31;
        const int r0 = w * 16 + (lane >> 2);
        const int c0 = nt * 8 + (lane & 3) * 2;
        float4 v;
        {
            float xx = g_tbl[idx[r0 * 64 + c0] * 12 + h];
            v.x = 16.f / (1.f + __expf(-xx));
            xx = g_tbl[idx[r0 * 64 + c0 + 1] * 12 + h];
            v.y = 16.f / (1.f + __expf(-xx));
            xx = g_tbl[idx[(r0 + 8) * 64 + c0] * 12 + h];
            v.z = 16.f / (1.f + __expf(-xx));
            xx = g_tbl[idx[(r0 + 8) * 64 + c0 + 1] * 12 + h];
            v.w = 16.f / (1.f + __expf(-xx));
        }
        g_biasf[gid] = v;
        return;
    }
    if (bid < 48 + nb_cvt) {
        const int i = (bid - 48) * 256 + tid;
        const float4 v = x4[i];
        __half2 h0 = __floats2half2_rn(v.x, v.y);
        __half2 h1 = __floats2half2_rn(v.z, v.w);
        ((uint2*)g_xh)[i] = make_uint2(*(uint32_t*)&h0, *(uint32_t*)&h1);
        return;
    }
    const int tb = bid - 48 - nb_cvt;
    const int z = tb / 576, rem = tb - z * 576;
    const float* w = z == 0 ? q_w : (z == 1 ? k_w : (z == 2 ? v_w : pw));
    __half* d = z < 3 ? (g_wh + (size_t)z * DIMC * DIMC) : g_wph;
    const int bx = (rem % 24) * 32, by = (rem / 24) * 32;
    const int x = tid & 31, y = tid >> 5;
#pragma unroll
    for (int i = 0; i < 32; i += 8) t[y + i][x] = w[(size_t)(by + y + i) * DIMC + bx + x];
    __syncthreads();
#pragma unroll
    for (int i = 0; i < 32; i += 8)
        d[(size_t)(bx + y + i) * DIMC + by + x] = __float2half_rn(t[x][y + i]);
}

// ---------------- tensor-core attention (R14 + 64-reg cap -> 8 CTA/SM) ----------------
#define ATTN_SMEM (3 * 8192 + 512)

__global__ void __launch_bounds__(128, 8) attn_kernel(
    const __half* __restrict__ Q, const __half* __restrict__ K,
    const __half* __restrict__ V, const float* __restrict__ LS,
    __half* __restrict__ O) {
    extern __shared__ char sm[];
    const uint32_t sq = smem_u32(sm);
    const uint32_t sk = sq + 8192;
    const uint32_t sv = sk + 8192;
    const uint32_t sp = sq;                // P overlays Q (rows warp-private post-S)
    float* qn = (float*)(sm + 3 * 8192);
    float* kn = qn + 64;

    const int b = blockIdx.x, h = blockIdx.y;
    const int t = threadIdx.x;
    const int lane = t & 31, warp = t >> 5;
    const size_t base = ((size_t)b * NTOK) * DIMC + h * DH;

#pragma unroll
    for (int i = 0; i < 12; i++) {
        const int idx = t + i * 128;
        const int tens = idx >> 9, rem = idx & 511;
        const int row = rem >> 3, ch = rem & 7;
        const __half* src = (tens == 0 ? Q : (tens == 1 ? K : V)) + base + (size_t)row * DIMC + ch * 8;
        const uint32_t dst = (tens == 0 ? sq : (tens == 1 ? sk : sv)) + ASW(row, ch * 16);
        cp16(dst, src);
    }
    cp_commit();
    cp_wait0();
    __syncthreads();

    // norms
    {
        const int row = t & 63;
        const uint32_t src = (t < 64 ? sq : sk);
        float s = 0.f;
#pragma unroll
        for (int ch = 0; ch < 8; ch++) {
            uint4 u;
            asm volatile("ld.shared.v4.u32 {%0,%1,%2,%3}, [%4];"
                         : "=r"(u.x), "=r"(u.y), "=r"(u.z), "=r"(u.w)
                         : "r"(src + ASW(row, ch * 16)));
            const uint32_t uu[4] = {u.x, u.y, u.z, u.w};
#pragma unroll
            for (int q2 = 0; q2 < 4; q2++) {
                float2 f = __half22float2(*(const __half2*)&uu[q2]);
                s += f.x * f.x + f.y * f.y;
            }
        }
        if (t < 64) qn[row] = sqrtf(s);
        else kn[row] = sqrtf(s);
    }
    // no barrier: warp proceeds to S MMAs

    const float scale = fmaxf(LS[h], 0.01f);
    const int m0 = warp * 16;
    const int l15 = lane & 15, lhb = (lane >> 4) * 16;

    float acc[8][4];
#pragma unroll
    for (int n = 0; n < 8; n++)
#pragma unroll
        for (int k = 0; k < 4; k++) acc[n][k] = 0.f;
#pragma unroll
    for (int ks = 0; ks < 4; ks++) {
        const int kb = ks * 32;
        uint32_t a[4];
        ldsm4(a[0], a[1], a[2], a[3], sq + ASW(m0 + l15, kb + lhb));
#pragma unroll
        for (int jb = 0; jb < 4; jb++) {
            uint32_t bfr[4];
            ldsm4(bfr[0], bfr[1], bfr[2], bfr[3], sk + ASW(jb * 16 + l15, kb + lhb));
            mma_f16(acc[jb * 2], a, bfr[0], bfr[2]);
            mma_f16(acc[jb * 2 + 1], a, bfr[1], bfr[3]);
        }
    }

    __syncthreads();   // norms visible; q reads done (overlay-safe)

    const int i0 = m0 + (lane >> 2);
    const float qn0 = qn[i0], qn1 = qn[i0 + 8];
    const float4* bgf = g_biasf + ((h * 4 + warp) * 8) * 32;
#pragma unroll
    for (int nt = 0; nt < 8; nt++) {
        const int c0 = nt * 8 + (lane & 3) * 2;
        const float4 bv = bgf[nt * 32 + lane];
        const float k0v = kn[c0], k1v = kn[c0 + 1];
        const float d00 = fmaxf(qn0 * k0v, 1e-6f), d01 = fmaxf(qn0 * k1v, 1e-6f);
        const float d10 = fmaxf(qn1 * k0v, 1e-6f), d11 = fmaxf(qn1 * k1v, 1e-6f);
        acc[nt][0] = acc[nt][0] / d00 * scale + bv.x;
        acc[nt][1] = acc[nt][1] / d01 * scale + bv.y;
        acc[nt][2] = acc[nt][2] / d10 * scale + bv.z;
        acc[nt][3] = acc[nt][3] / d11 * scale + bv.w;
    }

    float mx0 = -1e30f, mx1 = -1e30f;
#pragma unroll
    for (int nt = 0; nt < 8; nt++) {
        mx0 = fmaxf(mx0, fmaxf(acc[nt][0], acc[nt][1]));
        mx1 = fmaxf(mx1, fmaxf(acc[nt][2], acc[nt][3]));
    }
    mx0 = fmaxf(mx0, __shfl_xor_sync(0xffffffffu, mx0, 1));
    mx0 = fmaxf(mx0, __shfl_xor_sync(0xffffffffu, mx0, 2));
    mx1 = fmaxf(mx1, __shfl_xor_sync(0xffffffffu, mx1, 1));
    mx1 = fmaxf(mx1, __shfl_xor_sync(0xffffffffu, mx1, 2));
    float s0 = 0.f, s1 = 0.f;
#pragma unroll
    for (int nt = 0; nt < 8; nt++) {
        acc[nt][0] = __expf(acc[nt][0] - mx0);
        acc[nt][1] = __expf(acc[nt][1] - mx0);
        acc[nt][2] = __expf(acc[nt][2] - mx1);
        acc[nt][3] = __expf(acc[nt][3] - mx1);
        s0 += acc[nt][0] + acc[nt][1];
        s1 += acc[nt][2] + acc[nt][3];
    }
    s0 += __shfl_xor_sync(0xffffffffu, s0, 1);
    s0 += __shfl_xor_sync(0xffffffffu, s0, 2);
    s1 += __shfl_xor_sync(0xffffffffu, s1, 1);
    s1 += __shfl_xor_sync(0xffffffffu, s1, 2);
    const float inv0 = 1.f / s0, inv1 = 1.f / s1;

#pragma unroll
    for (int nt = 0; nt < 8; nt++) {
        const int c0 = nt * 8 + (lane & 3) * 2;
        __half2 h0 = __floats2half2_rn(acc[nt][0] * inv0, acc[nt][1] * inv0);
        __half2 h1 = __floats2half2_rn(acc[nt][2] * inv1, acc[nt][3] * inv1);
        asm volatile("st.shared.b32 [%0], %1;" ::"r"(sp + ASW(i0, c0 * 2)), "r"(*(uint32_t*)&h0));
        asm volatile("st.shared.b32 [%0], %1;" ::"r"(sp + ASW(i0 + 8, c0 * 2)), "r"(*(uint32_t*)&h1));
    }
    __syncwarp();

    float oc[8][4];
#pragma unroll
    for (int n = 0; n < 8; n++)
#pragma unroll
        for (int k = 0; k < 4; k++) oc[n][k] = 0.f;
#pragma unroll
    for (int ks = 0; ks < 4; ks++) {
        const int kb = ks * 32;
        uint32_t a[4];
        ldsm4(a[0], a[1], a[2], a[3], sp + ASW(m0 + l15, kb + lhb));
#pragma unroll
        for (int db = 0; db < 4; db++) {
            uint32_t bfr[4];
            ldsm4t(bfr[0], bfr[1], bfr[2], bfr[3], sv + ASW(ks * 16 + l15, db * 32 + lhb));
            mma_f16(oc[db * 2], a, bfr[0], bfr[1]);
            mma_f16(oc[db * 2 + 1], a, bfr[2], bfr[3]);
        }
    }

#pragma unroll
    for (int nt = 0; nt < 8; nt++) {
        const int d0 = nt * 8 + (lane & 3) * 2;
        __half2 h0 = __floats2half2_rn(oc[nt][0], oc[nt][1]);
        __half2 h1 = __floats2half2_rn(oc[nt][2], oc[nt][3]);
        *(__half2*)&O[base + (size_t)i0 * DIMC + d0] = h0;
        *(__half2*)&O[base + (size_t)(i0 + 8) * DIMC + d0] = h1;
    }
}

// ---------------- launch ----------------
extern "C" void kernel_launch(void* const* d_in, const int* in_sizes, int n_in,
                              void* d_out, int out_size) {
    const float* x   = (const float*)d_in[0];
    const float* q_w = (const float*)d_in[1];
    const float* q_b = (const float*)d_in[2];
    const float* k_w = (const float*)d_in[3];
    const float* v_w = (const float*)d_in[4];
    const float* v_b = (const float*)d_in[5];
    const float* cw1 = (const float*)d_in[6];
    const float* cb1 = (const float*)d_in[7];
    const float* cw2 = (const float*)d_in[8];
    const float* cb2 = (const float*)d_in[9];
    const float* ls  = (const float*)d_in[10];
    const float* pw  = (const float*)d_in[11];
    const float* pb  = (const float*)d_in[12];
    const float* tab = (const float*)d_in[13];
    const int*   idx = (const int*)d_in[14];
    float* out = (float*)d_out;

    const int rows = in_sizes[0] / DIMC;  // 65536
    const int B = rows / NTOK;            // 1024

    __half *dqh, *dkh, *dvh, *dxh, *dch, *dwh, *dwph;
    cudaGetSymbolAddress((void**)&dqh, g_qh);
    cudaGetSymbolAddress((void**)&dkh, g_kh);
    cudaGetSymbolAddress((void**)&dvh, g_vh);
    cudaGetSymbolAddress((void**)&dxh, g_xh);
    cudaGetSymbolAddress((void**)&dch, g_ch);
    cudaGetSymbolAddress((void**)&dwh, g_wh);
    cudaGetSymbolAddress((void**)&dwph, g_wph);

    cudaFuncSetAttribute(hgemm<__half>, cudaFuncAttributeMaxDynamicSharedMemorySize, HG_SMEM);
    cudaFuncSetAttribute(hgemm<float>, cudaFuncAttributeMaxDynamicSharedMemorySize, HG_SMEM);
    cudaFuncSetAttribute(attn_kernel, cudaFuncAttributeMaxDynamicSharedMemorySize, ATTN_SMEM);

    // 1: CPB MLP -> g_tbl
    cpb_kernel<<<343, 128>>>(tab, cw1, cb1, cw2, cb2);

    // 2: fused prep (fragment-ordered bias + x->fp16 + 4 weight transposes)
    const int n4 = rows * DIMC / 4;
    const int nb_cvt = n4 / 256;
    prep_kernel<<<48 + nb_cvt + 4 * 576, 256>>>(idx, (const float4*)x, nb_cvt,
                                                q_w, k_w, v_w, pw);

    // 3: fused QKV GEMM: [65536,768] x [768,2304] -> q,k,v (fp16)
    hgemm<__half><<<18 * (rows / 128), 256, HG_SMEM>>>(dxh, dwh, 18, q_b, nullptr, v_b,
                                                       dqh, dkh, dvh);

    // 4: tensor-core attention -> ctx (fp16)   [profiled launch]
    dim3 ga(B, HEADS);
    attn_kernel<<<ga, 128, ATTN_SMEM>>>(dqh, dkh, dvh, ls, dch);

    // 5: proj GEMM -> out (fp32)
    hgemm<float><<<6 * (rows / 128), 256, HG_SMEM>>>(dch, dwph, 6, pb, pb, pb,
                                                     out, out, out);
}

// round 16
// speedup vs baseline: 1.0647x; 1.0107x over previous
#include <cuda_runtime.h>
#include <cuda_fp16.h>
#include <cstdint>

#define DIMC 768
#define HEADS 12
#define NTOK 64
#define DH 64

// ---------------- scratch (device globals) ----------------
__device__ __half g_qh[65536 * 768];
__device__ __half g_kh[65536 * 768];
__device__ __half g_vh[65536 * 768];
__device__ __half g_xh[65536 * 768];
__device__ __half g_ch[65536 * 768];
__device__ __half g_wh[2304 * 768];    // qkv weights transposed [n][k] fp16
__device__ __half g_wph[768 * 768];    // proj weight transposed fp16
__device__ float g_tbl[343 * 12];
__device__ float4 g_biasf[12 * 4 * 8 * 32];   // fragment-ordered bias [h][warp][nt][lane]

// ---------------- helpers ----------------
__device__ __forceinline__ uint32_t smem_u32(const void* p) {
    uint32_t a;
    asm("{ .reg .u64 t; cvta.to.shared.u64 t, %1; cvt.u32.u64 %0, t; }" : "=r"(a) : "l"(p));
    return a;
}
__device__ __forceinline__ void cp16(uint32_t s, const void* g) {
    asm volatile("cp.async.cg.shared.global [%0], [%1], 16;" ::"r"(s), "l"(g) : "memory");
}
__device__ __forceinline__ void cp_commit() { asm volatile("cp.async.commit_group;" ::: "memory"); }
__device__ __forceinline__ void cp_wait1() { asm volatile("cp.async.wait_group 1;" ::: "memory"); }
__device__ __forceinline__ void cp_wait0() { asm volatile("cp.async.wait_group 0;" ::: "memory"); }

__device__ __forceinline__ void ldsm4(uint32_t& r0, uint32_t& r1, uint32_t& r2, uint32_t& r3,
                                      uint32_t addr) {
    asm volatile("ldmatrix.sync.aligned.m8n8.x4.shared.b16 {%0,%1,%2,%3}, [%4];"
                 : "=r"(r0), "=r"(r1), "=r"(r2), "=r"(r3)
                 : "r"(addr));
}
__device__ __forceinline__ void ldsm4t(uint32_t& r0, uint32_t& r1, uint32_t& r2, uint32_t& r3,
                                       uint32_t addr) {
    asm volatile("ldmatrix.sync.aligned.m8n8.x4.trans.shared.b16 {%0,%1,%2,%3}, [%4];"
                 : "=r"(r0), "=r"(r1), "=r"(r2), "=r"(r3)
                 : "r"(addr));
}
__device__ __forceinline__ void mma_f16(float* c, const uint32_t* a, uint32_t b0, uint32_t b1) {
    asm volatile(
        "mma.sync.aligned.m16n8k16.row.col.f32.f16.f16.f32 "
        "{%0,%1,%2,%3},{%4,%5,%6,%7},{%8,%9},{%0,%1,%2,%3};"
        : "+f"(c[0]), "+f"(c[1]), "+f"(c[2]), "+f"(c[3])
        : "r"(a[0]), "r"(a[1]), "r"(a[2]), "r"(a[3]), "r"(b0), "r"(b1));
}

#define ASW(row, colbytes) ((row) * 128 + (((colbytes)) ^ (((row) & 7) << 4)))

// ================= hgemm (R8 proven): CTA 128x128, 8 warps x (64x32), 3-stage, 1 sync ======
#define BK 64
#define STG_BYTES 32768
#define NSTG 3
#define HG_SMEM (NSTG * STG_BYTES)
#define NKT (DIMC / BK)

template <typename OutT>
__global__ void __launch_bounds__(256, 2) hgemm(
    const __half* __restrict__ A, const __half* __restrict__ Bt, int nbn,
    const float* __restrict__ biasQ, const float* __restrict__ biasK,
    const float* __restrict__ biasV,
    OutT* __restrict__ out0, OutT* __restrict__ out1, OutT* __restrict__ out2) {
    extern __shared__ char smem[];
    const uint32_t sb = smem_u32(smem);
    const int tid = threadIdx.x;
    const int lane = tid & 31, warp = tid >> 5;
    const int bn = blockIdx.x % nbn, bm = blockIdx.x / nbn;
    const int wm = (warp & 1) * 64, wn = (warp >> 1) * 32;

    float acc[4][4][4];
#pragma unroll
    for (int i = 0; i < 4; i++)
#pragma unroll
        for (int j = 0; j < 4; j++)
#pragma unroll
            for (int k = 0; k < 4; k++) acc[i][j][k] = 0.f;

    const __half* Ab = A + (size_t)(bm * 128) * DIMC;
    const __half* Bb = Bt + (size_t)(bn * 128) * DIMC;

    auto load_stage = [&](int kt, int s) {
        const uint32_t st = sb + s * STG_BYTES;
#pragma unroll
        for (int i = 0; i < 8; i++) {
            const int c = tid + i * 256;
            if (c < 1024) {
                const int row = c >> 3, ch = c & 7;
                cp16(st + ASW(row, ch * 16), Ab + (size_t)row * DIMC + kt * BK + ch * 8);
            } else {
                const int cb = c - 1024;
                const int row = cb >> 3, ch = cb & 7;
                cp16(st + 16384 + ASW(row, ch * 16), Bb + (size_t)row * DIMC + kt * BK + ch * 8);
            }
        }
        cp_commit();
    };

    load_stage(0, 0);
    load_stage(1, 1);

    const int l15 = lane & 15, lh = (lane >> 4) * 16;
    int rs = 0, ws = 2;

    for (int kt = 0; kt < NKT; kt++) {
        cp_wait1();
        __syncthreads();
        if (kt + 2 < NKT) load_stage(kt + 2, ws);
        else cp_commit();

        const uint32_t sA = sb + rs * STG_BYTES;
        const uint32_t sB = sA + 16384;

#pragma unroll
        for (int ks = 0; ks < 4; ks++) {
            const int kb = ks * 32;
            uint32_t af[4][4], bf[2][4];
#pragma unroll
            for (int mt = 0; mt < 4; mt++) {
                const int row = wm + mt * 16 + l15;
                ldsm4(af[mt][0], af[mt][1], af[mt][2], af[mt][3], sA + ASW(row, kb + lh));
            }
#pragma unroll
            for (int bt = 0; bt < 2; bt++) {
                const int row = wn + bt * 16 + l15;
                ldsm4(bf[bt][0], bf[bt][1], bf[bt][2], bf[bt][3], sB + ASW(row, kb + lh));
            }
#pragma unroll
            for (int mt = 0; mt < 4; mt++) {
#pragma unroll
                for (int nt = 0; nt < 4; nt++) {
                    const int bt = nt >> 1, od = nt & 1;
                    mma_f16(acc[mt][nt], af[mt], bf[bt][od], bf[bt][od + 2]);
                }
            }
        }
        rs = (rs == 2) ? 0 : rs + 1;
        ws = (ws == 2) ? 0 : ws + 1;
    }

    const int matsel = (bn * 128) / DIMC;
    OutT* dst = matsel == 0 ? out0 : (matsel == 1 ? out1 : out2);
    const float* bp = matsel == 0 ? biasQ : (matsel == 1 ? biasK : biasV);
    const int lcbase = bn * 128 - matsel * DIMC;
#pragma unroll
    for (int mt = 0; mt < 4; mt++) {
#pragma unroll
        for (int nt = 0; nt < 4; nt++) {
            const int row = bm * 128 + wm + mt * 16 + (lane >> 2);
            const int tcol = wn + nt * 8 + (lane & 3) * 2;
            const int lc = lcbase + tcol;
            const float b0 = bp ? bp[lc] : 0.f;
            const float b1 = bp ? bp[lc + 1] : 0.f;
            if (sizeof(OutT) == 4) {
                float2 v0 = make_float2(acc[mt][nt][0] + b0, acc[mt][nt][1] + b1);
                float2 v1 = make_float2(acc[mt][nt][2] + b0, acc[mt][nt][3] + b1);
                *(float2*)&((float*)dst)[(size_t)row * DIMC + lc] = v0;
                *(float2*)&((float*)dst)[(size_t)(row + 8) * DIMC + lc] = v1;
            } else {
                __half2 h0 = __floats2half2_rn(acc[mt][nt][0] + b0, acc[mt][nt][1] + b1);
                __half2 h1 = __floats2half2_rn(acc[mt][nt][2] + b0, acc[mt][nt][3] + b1);
                *(__half2*)&((__half*)dst)[(size_t)row * DIMC + lc] = h0;
                *(__half2*)&((__half*)dst)[(size_t)(row + 8) * DIMC + lc] = h1;
            }
        }
    }
}

// ---------------- CPB MLP (launch 1) ----------------
__global__ void cpb_kernel(const float* __restrict__ tabl, const float* __restrict__ w1,
                           const float* __restrict__ b1, const float* __restrict__ w2,
                           const float* __restrict__ b2) {
    __shared__ float red[128 * 12];
    const int r = blockIdx.x;
    const int t = threadIdx.x;
    const float t0 = tabl[r * 3 + 0], t1 = tabl[r * 3 + 1], t2 = tabl[r * 3 + 2];
    float part[12];
#pragma unroll
    for (int hh = 0; hh < 12; hh++) part[hh] = 0.f;
    for (int j = t; j < 512; j += 128) {
        float h = t0 * w1[j] + t1 * w1[512 + j] + t2 * w1[1024 + j] + b1[j];
        h = fmaxf(h, 0.f);
#pragma unroll
        for (int hh = 0; hh < 12; hh++) part[hh] += h * w2[j * 12 + hh];
    }
#pragma unroll
    for (int hh = 0; hh < 12; hh++) red[t * 12 + hh] = part[hh];
    __syncthreads();
    if (t < 12) {
        float s = b2[t];
        for (int i = 0; i < 128; i++) s += red[i * 12 + t];
        g_tbl[r * 12 + t] = s;
    }
}

// ---------------- mega-prep (launch 2): biasf + x->fp16 + 4 weight transposes ----------------
__global__ void prep_kernel(const int* __restrict__ idx,
                            const float4* __restrict__ x4, int nb_cvt,
                            const float* __restrict__ q_w, const float* __restrict__ k_w,
                            const float* __restrict__ v_w, const float* __restrict__ pw) {
    __shared__ float t[32][33];
    const int bid = blockIdx.x;
    const int tid = threadIdx.x;

    if (bid < 48) {
        const int gid = bid * 256 + tid;           // 0..12287
        const int h = gid >> 10;
        const int rem = gid & 1023;
        const int w = rem >> 8;
        const int rem2 = rem & 255;
        const int nt = rem2 >> 5, lane = rem2 & 31;
        const int r0 = w * 16 + (lane >> 2);
        const int c0 = nt * 8 + (lane & 3) * 2;
        float4 v;
        {
            float xx = g_tbl[idx[r0 * 64 + c0] * 12 + h];
            v.x = 16.f / (1.f + __expf(-xx));
            xx = g_tbl[idx[r0 * 64 + c0 + 1] * 12 + h];
            v.y = 16.f / (1.f + __expf(-xx));
            xx = g_tbl[idx[(r0 + 8) * 64 + c0] * 12 + h];
            v.z = 16.f / (1.f + __expf(-xx));
            xx = g_tbl[idx[(r0 + 8) * 64 + c0 + 1] * 12 + h];
            v.w = 16.f / (1.f + __expf(-xx));
        }
        g_biasf[gid] = v;
        return;
    }
    if (bid < 48 + nb_cvt) {
        const int i = (bid - 48) * 256 + tid;
        const float4 v = x4[i];
        __half2 h0 = __floats2half2_rn(v.x, v.y);
        __half2 h1 = __floats2half2_rn(v.z, v.w);
        ((uint2*)g_xh)[i] = make_uint2(*(uint32_t*)&h0, *(uint32_t*)&h1);
        return;
    }
    const int tb = bid - 48 - nb_cvt;
    const int z = tb / 576, rem = tb - z * 576;
    const float* w = z == 0 ? q_w : (z == 1 ? k_w : (z == 2 ? v_w : pw));
    __half* d = z < 3 ? (g_wh + (size_t)z * DIMC * DIMC) : g_wph;
    const int bx = (rem % 24) * 32, by = (rem / 24) * 32;
    const int x = tid & 31, y = tid >> 5;
#pragma unroll
    for (int i = 0; i < 32; i += 8) t[y + i][x] = w[(size_t)(by + y + i) * DIMC + bx + x];
    __syncthreads();
#pragma unroll
    for (int i = 0; i < 32; i += 8)
        d[(size_t)(bx + y + i) * DIMC + by + x] = __float2half_rn(t[x][y + i]);
}

// ---------------- tensor-core attention (R15 + reciprocal norms, no fdiv) ----------------
#define ATTN_SMEM (3 * 8192 + 512)

__global__ void __launch_bounds__(128, 8) attn_kernel(
    const __half* __restrict__ Q, const __half* __restrict__ K,
    const __half* __restrict__ V, const float* __restrict__ LS,
    __half* __restrict__ O) {
    extern __shared__ char sm[];
    const uint32_t sq = smem_u32(sm);
    const uint32_t sk = sq + 8192;
    const uint32_t sv = sk + 8192;
    const uint32_t sp = sq;                // P overlays Q (rows warp-private post-S)
    float* qn = (float*)(sm + 3 * 8192);   // reciprocal q norms
    float* kn = qn + 64;                   // reciprocal k norms

    const int b = blockIdx.x, h = blockIdx.y;
    const int t = threadIdx.x;
    const int lane = t & 31, warp = t >> 5;
    const size_t base = ((size_t)b * NTOK) * DIMC + h * DH;

#pragma unroll
    for (int i = 0; i < 12; i++) {
        const int idx = t + i * 128;
        const int tens = idx >> 9, rem = idx & 511;
        const int row = rem >> 3, ch = rem & 7;
        const __half* src = (tens == 0 ? Q : (tens == 1 ? K : V)) + base + (size_t)row * DIMC + ch * 8;
        const uint32_t dst = (tens == 0 ? sq : (tens == 1 ? sk : sv)) + ASW(row, ch * 16);
        cp16(dst, src);
    }
    cp_commit();
    cp_wait0();
    __syncthreads();

    // reciprocal norms (rsqrt; no divides downstream)
    {
        const int row = t & 63;
        const uint32_t src = (t < 64 ? sq : sk);
        float s = 0.f;
#pragma unroll
        for (int ch = 0; ch < 8; ch++) {
            uint4 u;
            asm volatile("ld.shared.v4.u32 {%0,%1,%2,%3}, [%4];"
                         : "=r"(u.x), "=r"(u.y), "=r"(u.z), "=r"(u.w)
                         : "r"(src + ASW(row, ch * 16)));
            const uint32_t uu[4] = {u.x, u.y, u.z, u.w};
#pragma unroll
            for (int q2 = 0; q2 < 4; q2++) {
                float2 f = __half22float2(*(const __half2*)&uu[q2]);
                s += f.x * f.x + f.y * f.y;
            }
        }
        if (t < 64) qn[row] = rsqrtf(s);
        else kn[row] = rsqrtf(s);
    }
    // no barrier: warp proceeds to S MMAs

    const float scale = fmaxf(LS[h], 0.01f);
    const int m0 = warp * 16;
    const int l15 = lane & 15, lhb = (lane >> 4) * 16;

    float acc[8][4];
#pragma unroll
    for (int n = 0; n < 8; n++)
#pragma unroll
        for (int k = 0; k < 4; k++) acc[n][k] = 0.f;
#pragma unroll
    for (int ks = 0; ks < 4; ks++) {
        const int kb = ks * 32;
        uint32_t a[4];
        ldsm4(a[0], a[1], a[2], a[3], sq + ASW(m0 + l15, kb + lhb));
#pragma unroll
        for (int jb = 0; jb < 4; jb++) {
            uint32_t bfr[4];
            ldsm4(bfr[0], bfr[1], bfr[2], bfr[3], sk + ASW(jb * 16 + l15, kb + lhb));
            mma_f16(acc[jb * 2], a, bfr[0], bfr[2]);
            mma_f16(acc[jb * 2 + 1], a, bfr[1], bfr[3]);
        }
    }

    __syncthreads();   // norms visible; q reads done (overlay-safe)

    const int i0 = m0 + (lane >> 2);
    // scale folded into reciprocal q-norm; clip transformed: min(rq*rk,1e6)*scale
    const float srq0 = qn[i0] * scale, srq1 = qn[i0 + 8] * scale;
    const float cl = 1e6f * scale;
    const float4* bgf = g_biasf + ((h * 4 + warp) * 8) * 32;
#pragma unroll
    for (int nt = 0; nt < 8; nt++) {
        const int c0 = nt * 8 + (lane & 3) * 2;
        const float4 bv = bgf[nt * 32 + lane];
        const float rk0 = kn[c0], rk1 = kn[c0 + 1];
        acc[nt][0] = acc[nt][0] * fminf(srq0 * rk0, cl) + bv.x;
        acc[nt][1] = acc[nt][1] * fminf(srq0 * rk1, cl) + bv.y;
        acc[nt][2] = acc[nt][2] * fminf(srq1 * rk0, cl) + bv.z;
        acc[nt][3] = acc[nt][3] * fminf(srq1 * rk1, cl) + bv.w;
    }

    float mx0 = -1e30f, mx1 = -1e30f;
#pragma unroll
    for (int nt = 0; nt < 8; nt++) {
        mx0 = fmaxf(mx0, fmaxf(acc[nt][0], acc[nt][1]));
        mx1 = fmaxf(mx1, fmaxf(acc[nt][2], acc[nt][3]));
    }
    mx0 = fmaxf(mx0, __shfl_xor_sync(0xffffffffu, mx0, 1));
    mx0 = fmaxf(mx0, __shfl_xor_sync(0xffffffffu, mx0, 2));
    mx1 = fmaxf(mx1, __shfl_xor_sync(0xffffffffu, mx1, 1));
    mx1 = fmaxf(mx1, __shfl_xor_sync(0xffffffffu, mx1, 2));
    float s0 = 0.f, s1 = 0.f;
#pragma unroll
    for (int nt = 0; nt < 8; nt++) {
        acc[nt][0] = __expf(acc[nt][0] - mx0);
        acc[nt][1] = __expf(acc[nt][1] - mx0);
        acc[nt][2] = __expf(acc[nt][2] - mx1);
        acc[nt][3] = __expf(acc[nt][3] - mx1);
        s0 += acc[nt][0] + acc[nt][1];
        s1 += acc[nt][2] + acc[nt][3];
    }
    s0 += __shfl_xor_sync(0xffffffffu, s0, 1);
    s0 += __shfl_xor_sync(0xffffffffu, s0, 2);
    s1 += __shfl_xor_sync(0xffffffffu, s1, 1);
    s1 += __shfl_xor_sync(0xffffffffu, s1, 2);
    const float inv0 = 1.f / s0, inv1 = 1.f / s1;

#pragma unroll
    for (int nt = 0; nt < 8; nt++) {
        const int c0 = nt * 8 + (lane & 3) * 2;
        __half2 h0 = __floats2half2_rn(acc[nt][0] * inv0, acc[nt][1] * inv0);
        __half2 h1 = __floats2half2_rn(acc[nt][2] * inv1, acc[nt][3] * inv1);
        asm volatile("st.shared.b32 [%0], %1;" ::"r"(sp + ASW(i0, c0 * 2)), "r"(*(uint32_t*)&h0));
        asm volatile("st.shared.b32 [%0], %1;" ::"r"(sp + ASW(i0 + 8, c0 * 2)), "r"(*(uint32_t*)&h1));
    }
    __syncwarp();

    float oc[8][4];
#pragma unroll
    for (int n = 0; n < 8; n++)
#pragma unroll
        for (int k = 0; k < 4; k++) oc[n][k] = 0.f;
#pragma unroll
    for (int ks = 0; ks < 4; ks++) {
        const int kb = ks * 32;
        uint32_t a[4];
        ldsm4(a[0], a[1], a[2], a[3], sp + ASW(m0 + l15, kb + lhb));
#pragma unroll
        for (int db = 0; db < 4; db++) {
            uint32_t bfr[4];
            ldsm4t(bfr[0], bfr[1], bfr[2], bfr[3], sv + ASW(ks * 16 + l15, db * 32 + lhb));
            mma_f16(oc[db * 2], a, bfr[0], bfr[1]);
            mma_f16(oc[db * 2 + 1], a, bfr[2], bfr[3]);
        }
    }

#pragma unroll
    for (int nt = 0; nt < 8; nt++) {
        const int d0 = nt * 8 + (lane & 3) * 2;
        __half2 h0 = __floats2half2_rn(oc[nt][0], oc[nt][1]);
        __half2 h1 = __floats2half2_rn(oc[nt][2], oc[nt][3]);
        *(__half2*)&O[base + (size_t)i0 * DIMC + d0] = h0;
        *(__half2*)&O[base + (size_t)(i0 + 8) * DIMC + d0] = h1;
    }
}

// ---------------- launch ----------------
extern "C" void kernel_launch(void* const* d_in, const int* in_sizes, int n_in,
                              void* d_out, int out_size) {
    const float* x   = (const float*)d_in[0];
    const float* q_w = (const float*)d_in[1];
    const float* q_b = (const float*)d_in[2];
    const float* k_w = (const float*)d_in[3];
    const float* v_w = (const float*)d_in[4];
    const float* v_b = (const float*)d_in[5];
    const float* cw1 = (const float*)d_in[6];
    const float* cb1 = (const float*)d_in[7];
    const float* cw2 = (const float*)d_in[8];
    const float* cb2 = (const float*)d_in[9];
    const float* ls  = (const float*)d_in[10];
    const float* pw  = (const float*)d_in[11];
    const float* pb  = (const float*)d_in[12];
    const float* tab = (const float*)d_in[13];
    const int*   idx = (const int*)d_in[14];
    float* out = (float*)d_out;

    const int rows = in_sizes[0] / DIMC;  // 65536
    const int B = rows / NTOK;            // 1024

    __half *dqh, *dkh, *dvh, *dxh, *dch, *dwh, *dwph;
    cudaGetSymbolAddress((void**)&dqh, g_qh);
    cudaGetSymbolAddress((void**)&dkh, g_kh);
    cudaGetSymbolAddress((void**)&dvh, g_vh);
    cudaGetSymbolAddress((void**)&dxh, g_xh);
    cudaGetSymbolAddress((void**)&dch, g_ch);
    cudaGetSymbolAddress((void**)&dwh, g_wh);
    cudaGetSymbolAddress((void**)&dwph, g_wph);

    cudaFuncSetAttribute(hgemm<__half>, cudaFuncAttributeMaxDynamicSharedMemorySize, HG_SMEM);
    cudaFuncSetAttribute(hgemm<float>, cudaFuncAttributeMaxDynamicSharedMemorySize, HG_SMEM);
    cudaFuncSetAttribute(attn_kernel, cudaFuncAttributeMaxDynamicSharedMemorySize, ATTN_SMEM);

    // 1: CPB MLP -> g_tbl
    cpb_kernel<<<343, 128>>>(tab, cw1, cb1, cw2, cb2);

    // 2: fused prep (fragment-ordered bias + x->fp16 + 4 weight transposes)
    const int n4 = rows * DIMC / 4;
    const int nb_cvt = n4 / 256;
    prep_kernel<<<48 + nb_cvt + 4 * 576, 256>>>(idx, (const float4*)x, nb_cvt,
                                                q_w, k_w, v_w, pw);

    // 3: fused QKV GEMM: [65536,768] x [768,2304] -> q,k,v (fp16)
    hgemm<__half><<<18 * (rows / 128), 256, HG_SMEM>>>(dxh, dwh, 18, q_b, nullptr, v_b,
                                                       dqh, dkh, dvh);

    // 4: tensor-core attention -> ctx (fp16)   [profiled launch]
    dim3 ga(B, HEADS);
    attn_kernel<<<ga, 128, ATTN_SMEM>>>(dqh, dkh, dvh, ls, dch);

    // 5: proj GEMM -> out (fp32)
    hgemm<float><<<6 * (rows / 128), 256, HG_SMEM>>>(dch, dwph, 6, pb, pb, pb,
                                                     out, out, out);
}

// round 17
// speedup vs baseline: 1.0659x; 1.0012x over previous
#include <cuda_runtime.h>
#include <cuda_fp16.h>
#include <cstdint>

#define DIMC 768
#define HEADS 12
#define NTOK 64
#define DH 64

// ---------------- scratch (device globals) ----------------
__device__ __half g_qh[65536 * 768];
__device__ __half g_kh[65536 * 768];
__device__ __half g_vh[65536 * 768];
__device__ __half g_xh[65536 * 768];
__device__ __half g_ch[65536 * 768];
__device__ __half g_wh[2304 * 768];    // qkv weights transposed [n][k] fp16
__device__ __half g_wph[768 * 768];    // proj weight transposed fp16
__device__ float g_tbl[343 * 12];
__device__ float4 g_biasf[12 * 4 * 8 * 32];   // fragment-ordered bias [h][warp][nt][lane]

// ---------------- helpers ----------------
__device__ __forceinline__ uint32_t smem_u32(const void* p) {
    uint32_t a;
    asm("{ .reg .u64 t; cvta.to.shared.u64 t, %1; cvt.u32.u64 %0, t; }" : "=r"(a) : "l"(p));
    return a;
}
__device__ __forceinline__ void cp16(uint32_t s, const void* g) {
    asm volatile("cp.async.cg.shared.global [%0], [%1], 16;" ::"r"(s), "l"(g) : "memory");
}
__device__ __forceinline__ void cp_commit() { asm volatile("cp.async.commit_group;" ::: "memory"); }
__device__ __forceinline__ void cp_wait1() { asm volatile("cp.async.wait_group 1;" ::: "memory"); }
__device__ __forceinline__ void cp_wait0() { asm volatile("cp.async.wait_group 0;" ::: "memory"); }

__device__ __forceinline__ void ldsm4(uint32_t& r0, uint32_t& r1, uint32_t& r2, uint32_t& r3,
                                      uint32_t addr) {
    asm volatile("ldmatrix.sync.aligned.m8n8.x4.shared.b16 {%0,%1,%2,%3}, [%4];"
                 : "=r"(r0), "=r"(r1), "=r"(r2), "=r"(r3)
                 : "r"(addr));
}
__device__ __forceinline__ void ldsm4t(uint32_t& r0, uint32_t& r1, uint32_t& r2, uint32_t& r3,
                                       uint32_t addr) {
    asm volatile("ldmatrix.sync.aligned.m8n8.x4.trans.shared.b16 {%0,%1,%2,%3}, [%4];"
                 : "=r"(r0), "=r"(r1), "=r"(r2), "=r"(r3)
                 : "r"(addr));
}
__device__ __forceinline__ void mma_f16(float* c, const uint32_t* a, uint32_t b0, uint32_t b1) {
    asm volatile(
        "mma.sync.aligned.m16n8k16.row.col.f32.f16.f16.f32 "
        "{%0,%1,%2,%3},{%4,%5,%6,%7},{%8,%9},{%0,%1,%2,%3};"
        : "+f"(c[0]), "+f"(c[1]), "+f"(c[2]), "+f"(c[3])
        : "r"(a[0]), "r"(a[1]), "r"(a[2]), "r"(a[3]), "r"(b0), "r"(b1));
}

#define ASW(row, colbytes) ((row) * 128 + (((colbytes)) ^ (((row) & 7) << 4)))

// ================= hgemm (R8 proven): CTA 128x128, 8 warps x (64x32), 3-stage, 1 sync ======
#define BK 64
#define STG_BYTES 32768
#define NSTG 3
#define HG_SMEM (NSTG * STG_BYTES)
#define NKT (DIMC / BK)

template <typename OutT>
__global__ void __launch_bounds__(256, 2) hgemm(
    const __half* __restrict__ A, const __half* __restrict__ Bt, int nbn,
    const float* __restrict__ biasQ, const float* __restrict__ biasK,
    const float* __restrict__ biasV,
    OutT* __restrict__ out0, OutT* __restrict__ out1, OutT* __restrict__ out2) {
    extern __shared__ char smem[];
    const uint32_t sb = smem_u32(smem);
    const int tid = threadIdx.x;
    const int lane = tid & 31, warp = tid >> 5;
    const int bn = blockIdx.x % nbn, bm = blockIdx.x / nbn;
    const int wm = (warp & 1) * 64, wn = (warp >> 1) * 32;

    float acc[4][4][4];
#pragma unroll
    for (int i = 0; i < 4; i++)
#pragma unroll
        for (int j = 0; j < 4; j++)
#pragma unroll
            for (int k = 0; k < 4; k++) acc[i][j][k] = 0.f;

    const __half* Ab = A + (size_t)(bm * 128) * DIMC;
    const __half* Bb = Bt + (size_t)(bn * 128) * DIMC;

    auto load_stage = [&](int kt, int s) {
        const uint32_t st = sb + s * STG_BYTES;
#pragma unroll
        for (int i = 0; i < 8; i++) {
            const int c = tid + i * 256;
            if (c < 1024) {
                const int row = c >> 3, ch = c & 7;
                cp16(st + ASW(row, ch * 16), Ab + (size_t)row * DIMC + kt * BK + ch * 8);
            } else {
                const int cb = c - 1024;
                const int row = cb >> 3, ch = cb & 7;
                cp16(st + 16384 + ASW(row, ch * 16), Bb + (size_t)row * DIMC + kt * BK + ch * 8);
            }
        }
        cp_commit();
    };

    load_stage(0, 0);
    load_stage(1, 1);

    const int l15 = lane & 15, lh = (lane >> 4) * 16;
    int rs = 0, ws = 2;

    for (int kt = 0; kt < NKT; kt++) {
        cp_wait1();
        __syncthreads();
        if (kt + 2 < NKT) load_stage(kt + 2, ws);
        else cp_commit();

        const uint32_t sA = sb + rs * STG_BYTES;
        const uint32_t sB = sA + 16384;

#pragma unroll
        for (int ks = 0; ks < 4; ks++) {
            const int kb = ks * 32;
            uint32_t af[4][4], bf[2][4];
#pragma unroll
            for (int mt = 0; mt < 4; mt++) {
                const int row = wm + mt * 16 + l15;
                ldsm4(af[mt][0], af[mt][1], af[mt][2], af[mt][3], sA + ASW(row, kb + lh));
            }
#pragma unroll
            for (int bt = 0; bt < 2; bt++) {
                const int row = wn + bt * 16 + l15;
                ldsm4(bf[bt][0], bf[bt][1], bf[bt][2], bf[bt][3], sB + ASW(row, kb + lh));
            }
#pragma unroll
            for (int mt = 0; mt < 4; mt++) {
#pragma unroll
                for (int nt = 0; nt < 4; nt++) {
                    const int bt = nt >> 1, od = nt & 1;
                    mma_f16(acc[mt][nt], af[mt], bf[bt][od], bf[bt][od + 2]);
                }
            }
        }
        rs = (rs == 2) ? 0 : rs + 1;
        ws = (ws == 2) ? 0 : ws + 1;
    }

    const int matsel = (bn * 128) / DIMC;
    OutT* dst = matsel == 0 ? out0 : (matsel == 1 ? out1 : out2);
    const float* bp = matsel == 0 ? biasQ : (matsel == 1 ? biasK : biasV);
    const int lcbase = bn * 128 - matsel * DIMC;
#pragma unroll
    for (int mt = 0; mt < 4; mt++) {
#pragma unroll
        for (int nt = 0; nt < 4; nt++) {
            const int row = bm * 128 + wm + mt * 16 + (lane >> 2);
            const int tcol = wn + nt * 8 + (lane & 3) * 2;
            const int lc = lcbase + tcol;
            const float b0 = bp ? bp[lc] : 0.f;
            const float b1 = bp ? bp[lc + 1] : 0.f;
            if (sizeof(OutT) == 4) {
                float2 v0 = make_float2(acc[mt][nt][0] + b0, acc[mt][nt][1] + b1);
                float2 v1 = make_float2(acc[mt][nt][2] + b0, acc[mt][nt][3] + b1);
                *(float2*)&((float*)dst)[(size_t)row * DIMC + lc] = v0;
                *(float2*)&((float*)dst)[(size_t)(row + 8) * DIMC + lc] = v1;
            } else {
                __half2 h0 = __floats2half2_rn(acc[mt][nt][0] + b0, acc[mt][nt][1] + b1);
                __half2 h1 = __floats2half2_rn(acc[mt][nt][2] + b0, acc[mt][nt][3] + b1);
                *(__half2*)&((__half*)dst)[(size_t)row * DIMC + lc] = h0;
                *(__half2*)&((__half*)dst)[(size_t)(row + 8) * DIMC + lc] = h1;
            }
        }
    }
}

// ---------------- CPB MLP (launch 1) ----------------
__global__ void cpb_kernel(const float* __restrict__ tabl, const float* __restrict__ w1,
                           const float* __restrict__ b1, const float* __restrict__ w2,
                           const float* __restrict__ b2) {
    __shared__ float red[128 * 12];
    const int r = blockIdx.x;
    const int t = threadIdx.x;
    const float t0 = tabl[r * 3 + 0], t1 = tabl[r * 3 + 1], t2 = tabl[r * 3 + 2];
    float part[12];
#pragma unroll
    for (int hh = 0; hh < 12; hh++) part[hh] = 0.f;
    for (int j = t; j < 512; j += 128) {
        float h = t0 * w1[j] + t1 * w1[512 + j] + t2 * w1[1024 + j] + b1[j];
        h = fmaxf(h, 0.f);
#pragma unroll
        for (int hh = 0; hh < 12; hh++) part[hh] += h * w2[j * 12 + hh];
    }
#pragma unroll
    for (int hh = 0; hh < 12; hh++) red[t * 12 + hh] = part[hh];
    __syncthreads();
    if (t < 12) {
        float s = b2[t];
        for (int i = 0; i < 128; i++) s += red[i * 12 + t];
        g_tbl[r * 12 + t] = s;
    }
}

// ---------------- mega-prep (launch 2): biasf + x->fp16 + 4 weight transposes ----------------
__global__ void prep_kernel(const int* __restrict__ idx,
                            const float4* __restrict__ x4, int nb_cvt,
                            const float* __restrict__ q_w, const float* __restrict__ k_w,
                            const float* __restrict__ v_w, const float* __restrict__ pw) {
    __shared__ float t[32][33];
    const int bid = blockIdx.x;
    const int tid = threadIdx.x;

    if (bid < 48) {
        const int gid = bid * 256 + tid;
        const int h = gid >> 10;
        const int rem = gid & 1023;
        const int w = rem >> 8;
        const int rem2 = rem & 255;
        const int nt = rem2 >> 5, lane = rem2 & 31;
        const int r0 = w * 16 + (lane >> 2);
        const int c0 = nt * 8 + (lane & 3) * 2;
        float4 v;
        {
            float xx = g_tbl[idx[r0 * 64 + c0] * 12 + h];
            v.x = 16.f / (1.f + __expf(-xx));
            xx = g_tbl[idx[r0 * 64 + c0 + 1] * 12 + h];
            v.y = 16.f / (1.f + __expf(-xx));
            xx = g_tbl[idx[(r0 + 8) * 64 + c0] * 12 + h];
            v.z = 16.f / (1.f + __expf(-xx));
            xx = g_tbl[idx[(r0 + 8) * 64 + c0 + 1] * 12 + h];
            v.w = 16.f / (1.f + __expf(-xx));
        }
        g_biasf[gid] = v;
        return;
    }
    if (bid < 48 + nb_cvt) {
        const int i = (bid - 48) * 256 + tid;
        const float4 v = x4[i];
        __half2 h0 = __floats2half2_rn(v.x, v.y);
        __half2 h1 = __floats2half2_rn(v.z, v.w);
        ((uint2*)g_xh)[i] = make_uint2(*(uint32_t*)&h0, *(uint32_t*)&h1);
        return;
    }
    const int tb = bid - 48 - nb_cvt;
    const int z = tb / 576, rem = tb - z * 576;
    const float* w = z == 0 ? q_w : (z == 1 ? k_w : (z == 2 ? v_w : pw));
    __half* d = z < 3 ? (g_wh + (size_t)z * DIMC * DIMC) : g_wph;
    const int bx = (rem % 24) * 32, by = (rem / 24) * 32;
    const int x = tid & 31, y = tid >> 5;
#pragma unroll
    for (int i = 0; i < 32; i += 8) t[y + i][x] = w[(size_t)(by + y + i) * DIMC + bx + x];
    __syncthreads();
#pragma unroll
    for (int i = 0; i < 32; i += 8)
        d[(size_t)(bx + y + i) * DIMC + by + x] = __float2half_rn(t[x][y + i]);
}

// ---------------- tensor-core attention (R16 + split V load + heads-fastest grid) ----------
#define ATTN_SMEM (3 * 8192 + 512)

__global__ void __launch_bounds__(128, 8) attn_kernel(
    const __half* __restrict__ Q, const __half* __restrict__ K,
    const __half* __restrict__ V, const float* __restrict__ LS,
    __half* __restrict__ O) {
    extern __shared__ char sm[];
    const uint32_t sq = smem_u32(sm);
    const uint32_t sk = sq + 8192;
    const uint32_t sv = sk + 8192;
    const uint32_t sp = sq;                // P overlays Q (rows warp-private post-S)
    float* qn = (float*)(sm + 3 * 8192);   // reciprocal q norms
    float* kn = qn + 64;                   // reciprocal k norms

    const int h = blockIdx.x, b = blockIdx.y;   // heads fastest for DRAM locality
    const int t = threadIdx.x;
    const int lane = t & 31, warp = t >> 5;
    const size_t base = ((size_t)b * NTOK) * DIMC + h * DH;

    // group 1: Q + K (needed first)
#pragma unroll
    for (int i = 0; i < 8; i++) {
        const int idx = t + i * 128;
        const int tens = idx >> 9, rem = idx & 511;
        const int row = rem >> 3, ch = rem & 7;
        const __half* src = (tens == 0 ? Q : K) + base + (size_t)row * DIMC + ch * 8;
        const uint32_t dst = (tens == 0 ? sq : sk) + ASW(row, ch * 16);
        cp16(dst, src);
    }
    cp_commit();
    // group 2: V (consumed only after softmax)
#pragma unroll
    for (int i = 0; i < 4; i++) {
        const int rem = t + i * 128;
        const int row = rem >> 3, ch = rem & 7;
        cp16(sv + ASW(row, ch * 16), V + base + (size_t)row * DIMC + ch * 8);
    }
    cp_commit();

    cp_wait1();        // Q+K ready; V still in flight
    __syncthreads();

    // reciprocal norms
    {
        const int row = t & 63;
        const uint32_t src = (t < 64 ? sq : sk);
        float s = 0.f;
#pragma unroll
        for (int ch = 0; ch < 8; ch++) {
            uint4 u;
            asm volatile("ld.shared.v4.u32 {%0,%1,%2,%3}, [%4];"
                         : "=r"(u.x), "=r"(u.y), "=r"(u.z), "=r"(u.w)
                         : "r"(src + ASW(row, ch * 16)));
            const uint32_t uu[4] = {u.x, u.y, u.z, u.w};
#pragma unroll
            for (int q2 = 0; q2 < 4; q2++) {
                float2 f = __half22float2(*(const __half2*)&uu[q2]);
                s += f.x * f.x + f.y * f.y;
            }
        }
        if (t < 64) qn[row] = rsqrtf(s);
        else kn[row] = rsqrtf(s);
    }
    // no barrier: warp proceeds to S MMAs

    const float scale = fmaxf(LS[h], 0.01f);
    const int m0 = warp * 16;
    const int l15 = lane & 15, lhb = (lane >> 4) * 16;

    float acc[8][4];
#pragma unroll
    for (int n = 0; n < 8; n++)
#pragma unroll
        for (int k = 0; k < 4; k++) acc[n][k] = 0.f;
#pragma unroll
    for (int ks = 0; ks < 4; ks++) {
        const int kb = ks * 32;
        uint32_t a[4];
        ldsm4(a[0], a[1], a[2], a[3], sq + ASW(m0 + l15, kb + lhb));
#pragma unroll
        for (int jb = 0; jb < 4; jb++) {
            uint32_t bfr[4];
            ldsm4(bfr[0], bfr[1], bfr[2], bfr[3], sk + ASW(jb * 16 + l15, kb + lhb));
            mma_f16(acc[jb * 2], a, bfr[0], bfr[2]);
            mma_f16(acc[jb * 2 + 1], a, bfr[1], bfr[3]);
        }
    }

    cp_wait0();        // V resident (overlapped with norms + S phase)
    __syncthreads();   // norms + V visible to all warps; q reads done (overlay-safe)

    const int i0 = m0 + (lane >> 2);
    const float srq0 = qn[i0] * scale, srq1 = qn[i0 + 8] * scale;
    const float cl = 1e6f * scale;
    const float4* bgf = g_biasf + ((h * 4 + warp) * 8) * 32;
#pragma unroll
    for (int nt = 0; nt < 8; nt++) {
        const int c0 = nt * 8 + (lane & 3) * 2;
        const float4 bv = bgf[nt * 32 + lane];
        const float rk0 = kn[c0], rk1 = kn[c0 + 1];
        acc[nt][0] = acc[nt][0] * fminf(srq0 * rk0, cl) + bv.x;
        acc[nt][1] = acc[nt][1] * fminf(srq0 * rk1, cl) + bv.y;
        acc[nt][2] = acc[nt][2] * fminf(srq1 * rk0, cl) + bv.z;
        acc[nt][3] = acc[nt][3] * fminf(srq1 * rk1, cl) + bv.w;
    }

    float mx0 = -1e30f, mx1 = -1e30f;
#pragma unroll
    for (int nt = 0; nt < 8; nt++) {
        mx0 = fmaxf(mx0, fmaxf(acc[nt][0], acc[nt][1]));
        mx1 = fmaxf(mx1, fmaxf(acc[nt][2], acc[nt][3]));
    }
    mx0 = fmaxf(mx0, __shfl_xor_sync(0xffffffffu, mx0, 1));
    mx0 = fmaxf(mx0, __shfl_xor_sync(0xffffffffu, mx0, 2));
    mx1 = fmaxf(mx1, __shfl_xor_sync(0xffffffffu, mx1, 1));
    mx1 = fmaxf(mx1, __shfl_xor_sync(0xffffffffu, mx1, 2));
    float s0 = 0.f, s1 = 0.f;
#pragma unroll
    for (int nt = 0; nt < 8; nt++) {
        acc[nt][0] = __expf(acc[nt][0] - mx0);
        acc[nt][1] = __expf(acc[nt][1] - mx0);
        acc[nt][2] = __expf(acc[nt][2] - mx1);
        acc[nt][3] = __expf(acc[nt][3] - mx1);
        s0 += acc[nt][0] + acc[nt][1];
        s1 += acc[nt][2] + acc[nt][3];
    }
    s0 += __shfl_xor_sync(0xffffffffu, s0, 1);
    s0 += __shfl_xor_sync(0xffffffffu, s0, 2);
    s1 += __shfl_xor_sync(0xffffffffu, s1, 1);
    s1 += __shfl_xor_sync(0xffffffffu, s1, 2);
    const float inv0 = 1.f / s0, inv1 = 1.f / s1;

#pragma unroll
    for (int nt = 0; nt < 8; nt++) {
        const int c0 = nt * 8 + (lane & 3) * 2;
        __half2 h0 = __floats2half2_rn(acc[nt][0] * inv0, acc[nt][1] * inv0);
        __half2 h1 = __floats2half2_rn(acc[nt][2] * inv1, acc[nt][3] * inv1);
        asm volatile("st.shared.b32 [%0], %1;" ::"r"(sp + ASW(i0, c0 * 2)), "r"(*(uint32_t*)&h0));
        asm volatile("st.shared.b32 [%0], %1;" ::"r"(sp + ASW(i0 + 8, c0 * 2)), "r"(*(uint32_t*)&h1));
    }
    __syncwarp();

    float oc[8][4];
#pragma unroll
    for (int n = 0; n < 8; n++)
#pragma unroll
        for (int k = 0; k < 4; k++) oc[n][k] = 0.f;
#pragma unroll
    for (int ks = 0; ks < 4; ks++) {
        const int kb = ks * 32;
        uint32_t a[4];
        ldsm4(a[0], a[1], a[2], a[3], sp + ASW(m0 + l15, kb + lhb));
#pragma unroll
        for (int db = 0; db < 4; db++) {
            uint32_t bfr[4];
            ldsm4t(bfr[0], bfr[1], bfr[2], bfr[3], sv + ASW(ks * 16 + l15, db * 32 + lhb));
            mma_f16(oc[db * 2], a, bfr[0], bfr[1]);
            mma_f16(oc[db * 2 + 1], a, bfr[2], bfr[3]);
        }
    }

#pragma unroll
    for (int nt = 0; nt < 8; nt++) {
        const int d0 = nt * 8 + (lane & 3) * 2;
        __half2 h0 = __floats2half2_rn(oc[nt][0], oc[nt][1]);
        __half2 h1 = __floats2half2_rn(oc[nt][2], oc[nt][3]);
        *(__half2*)&O[base + (size_t)i0 * DIMC + d0] = h0;
        *(__half2*)&O[base + (size_t)(i0 + 8) * DIMC + d0] = h1;
    }
}

// ---------------- launch ----------------
extern "C" void kernel_launch(void* const* d_in, const int* in_sizes, int n_in,
                              void* d_out, int out_size) {
    const float* x   = (const float*)d_in[0];
    const float* q_w = (const float*)d_in[1];
    const float* q_b = (const float*)d_in[2];
    const float* k_w = (const float*)d_in[3];
    const float* v_w = (const float*)d_in[4];
    const float* v_b = (const float*)d_in[5];
    const float* cw1 = (const float*)d_in[6];
    const float* cb1 = (const float*)d_in[7];
    const float* cw2 = (const float*)d_in[8];
    const float* cb2 = (const float*)d_in[9];
    const float* ls  = (const float*)d_in[10];
    const float* pw  = (const float*)d_in[11];
    const float* pb  = (const float*)d_in[12];
    const float* tab = (const float*)d_in[13];
    const int*   idx = (const int*)d_in[14];
    float* out = (float*)d_out;

    const int rows = in_sizes[0] / DIMC;  // 65536
    const int B = rows / NTOK;            // 1024

    __half *dqh, *dkh, *dvh, *dxh, *dch, *dwh, *dwph;
    cudaGetSymbolAddress((void**)&dqh, g_qh);
    cudaGetSymbolAddress((void**)&dkh, g_kh);
    cudaGetSymbolAddress((void**)&dvh, g_vh);
    cudaGetSymbolAddress((void**)&dxh, g_xh);
    cudaGetSymbolAddress((void**)&dch, g_ch);
    cudaGetSymbolAddress((void**)&dwh, g_wh);
    cudaGetSymbolAddress((void**)&dwph, g_wph);

    cudaFuncSetAttribute(hgemm<__half>, cudaFuncAttributeMaxDynamicSharedMemorySize, HG_SMEM);
    cudaFuncSetAttribute(hgemm<float>, cudaFuncAttributeMaxDynamicSharedMemorySize, HG_SMEM);
    cudaFuncSetAttribute(attn_kernel, cudaFuncAttributeMaxDynamicSharedMemorySize, ATTN_SMEM);

    // 1: CPB MLP -> g_tbl
    cpb_kernel<<<343, 128>>>(tab, cw1, cb1, cw2, cb2);

    // 2: fused prep (fragment-ordered bias + x->fp16 + 4 weight transposes)
    const int n4 = rows * DIMC / 4;
    const int nb_cvt = n4 / 256;
    prep_kernel<<<48 + nb_cvt + 4 * 576, 256>>>(idx, (const float4*)x, nb_cvt,
                                                q_w, k_w, v_w, pw);

    // 3: fused QKV GEMM: [65536,768] x [768,2304] -> q,k,v (fp16)
    hgemm<__half><<<18 * (rows / 128), 256, HG_SMEM>>>(dxh, dwh, 18, q_b, nullptr, v_b,
                                                       dqh, dkh, dvh);

    // 4: tensor-core attention -> ctx (fp16)   [profiled launch]
    dim3 ga(HEADS, B);
    attn_kernel<<<ga, 128, ATTN_SMEM>>>(dqh, dkh, dvh, ls, dch);

    // 5: proj GEMM -> out (fp32)
    hgemm<float><<<6 * (rows / 128), 256, HG_SMEM>>>(dch, dwph, 6, pb, pb, pb,
                                                     out, out, out);
}